// round 3
// baseline (speedup 1.0000x reference)
#include <cuda_runtime.h>
#include <math.h>
#include <stdint.h>

#define B_  4
#define S_  2048
#define H_  768
#define NH_ 12
#define D_  64
#define SCALE_ 0.125f   // 1/sqrt(64)

// Scratch, layout [b][h][s][d]
__device__ float g_Q[(size_t)B_ * NH_ * S_ * D_];
__device__ float g_K[(size_t)B_ * NH_ * S_ * D_];
__device__ float g_V[(size_t)B_ * NH_ * S_ * D_];
// Transposed weights [qkv][h][d][H]  and V [b][h][d][s]
__device__ float g_WT[(size_t)3 * NH_ * D_ * H_];
__device__ float g_VT[(size_t)B_ * NH_ * D_ * S_];

// ---------------------------------------------------------------------------
__device__ __forceinline__ float tf(float f) {
    uint32_t u;
    asm("cvt.rna.tf32.f32 %0, %1;" : "=r"(u) : "f"(f));
    return __uint_as_float(u);
}
__device__ __forceinline__ void mma_tf32(float c[4], float a0, float a1,
                                         float a2, float a3,
                                         float b0, float b1) {
    asm volatile(
        "mma.sync.aligned.m16n8k8.row.col.f32.tf32.tf32.f32 "
        "{%0,%1,%2,%3}, {%4,%5,%6,%7}, {%8,%9}, {%0,%1,%2,%3};"
        : "+f"(c[0]), "+f"(c[1]), "+f"(c[2]), "+f"(c[3])
        : "r"(__float_as_uint(a0)), "r"(__float_as_uint(a1)),
          "r"(__float_as_uint(a2)), "r"(__float_as_uint(a3)),
          "r"(__float_as_uint(b0)), "r"(__float_as_uint(b1)));
}

// Permuted-pair tile fill helper: cols j..j+7 of one row -> positions so that
// logical col j lands at (j&3)*2 + (j>>2)  (pairs (c, c+4) adjacent).
#define PERM_STORE(dst, v0, v1)                                          \
    do {                                                                 \
        float4 w0 = make_float4(tf((v0).x), tf((v1).x), tf((v0).y), tf((v1).y)); \
        float4 w1 = make_float4(tf((v0).z), tf((v1).z), tf((v0).w), tf((v1).w)); \
        *(float4*)(dst)       = w0;                                      \
        *(float4*)((dst) + 4) = w1;                                      \
    } while (0)

// ---------------------------------------------------------------------------
// Transpose W[h][H][D] -> g_WT[qkv][h][D][H]. grid (48, 36), 256 thr.
// ---------------------------------------------------------------------------
__global__ __launch_bounds__(256) void transpose_W(
    const float* __restrict__ Wq, const float* __restrict__ Wk,
    const float* __restrict__ Wv)
{
    const int qkv = blockIdx.y / NH_;
    const int h   = blockIdx.y % NH_;
    const float* W = (qkv == 0 ? Wq : (qkv == 1 ? Wk : Wv)) + (size_t)h * H_ * D_;
    float* WT = g_WT + (size_t)blockIdx.y * D_ * H_;

    const int kt = (blockIdx.x >> 1) * 32;   // k-tile (H dim)
    const int nt = (blockIdx.x & 1) * 32;    // n-tile (D dim)

    __shared__ float t[32][33];
    const int r  = threadIdx.x >> 3;          // 0..31
    const int c4 = (threadIdx.x & 7) * 4;     // 0,4,..28

    float4 v = *(const float4*)&W[(size_t)(kt + r) * D_ + nt + c4];
    t[r][c4 + 0] = v.x; t[r][c4 + 1] = v.y; t[r][c4 + 2] = v.z; t[r][c4 + 3] = v.w;
    __syncthreads();
    float4 o;
    o.x = t[c4 + 0][r]; o.y = t[c4 + 1][r]; o.z = t[c4 + 2][r]; o.w = t[c4 + 3][r];
    *(float4*)&WT[(size_t)(nt + r) * H_ + kt + c4] = o;
}

// ---------------------------------------------------------------------------
// Transpose g_V[bh][S][D] -> g_VT[bh][D][S]. grid (128, 48), 256 thr.
// ---------------------------------------------------------------------------
__global__ __launch_bounds__(256) void transpose_V()
{
    const int bh = blockIdx.y;
    const float* V = g_V + (size_t)bh * S_ * D_;
    float* VT = g_VT + (size_t)bh * D_ * S_;

    const int st = (blockIdx.x >> 1) * 32;   // seq tile
    const int dt = (blockIdx.x & 1) * 32;    // d tile

    __shared__ float t[32][33];
    const int r  = threadIdx.x >> 3;
    const int c4 = (threadIdx.x & 7) * 4;

    float4 v = *(const float4*)&V[(size_t)(st + r) * D_ + dt + c4];
    t[r][c4 + 0] = v.x; t[r][c4 + 1] = v.y; t[r][c4 + 2] = v.z; t[r][c4 + 3] = v.w;
    __syncthreads();
    float4 o;
    o.x = t[c4 + 0][r]; o.y = t[c4 + 1][r]; o.z = t[c4 + 2][r]; o.w = t[c4 + 3][r];
    *(float4*)&VT[(size_t)(dt + r) * S_ + st + c4] = o;
}

// ---------------------------------------------------------------------------
// QKV projection with tf32 mma. grid (64, 36), 256 thr (8 warps).
// Block tile: 128 rows x 64 cols. Warp tile: 32x32 (2 m-atoms x 4 n-atoms).
// Smem in permuted-pair layout, pitch 40 (40 % 32 == 8 -> LDS.64 conflict-free)
// ---------------------------------------------------------------------------
#define APITCH 40
__global__ __launch_bounds__(256, 2) void qkv_proj_tc(
    const float* __restrict__ e1, const float* __restrict__ e2,
    const float* __restrict__ e3,
    const float* __restrict__ bq, const float* __restrict__ bk,
    const float* __restrict__ bv)
{
    const int h   = blockIdx.y % NH_;
    const int qkv = blockIdx.y / NH_;
    const int grp = h >> 2;

    const float* WT   = g_WT + (size_t)blockIdx.y * D_ * H_;    // [D][H]
    const float* bias = (qkv == 0 ? bq : (qkv == 1 ? bk : bv)) + (size_t)h * D_;
    float*       out  = (qkv == 0 ? g_Q : (qkv == 1 ? g_K : g_V));
    const float* x    = (grp == 0 ? e1 : (grp == 1 ? e2 : e3));

    const int m0  = blockIdx.x * 128;
    const int tid = threadIdx.x;
    const int w    = tid >> 5;
    const int lane = tid & 31;
    const int g    = lane >> 2;
    const int c    = lane & 3;
    const int m0w  = (w >> 1) * 32;   // warp row offset
    const int n0w  = (w & 1) * 32;    // warp col offset

    __shared__ float As[128 * APITCH];   // [row][k]  permuted pairs
    __shared__ float Bs[64  * APITCH];   // [n=d][k]  permuted pairs

    float Cf[2][4][4] = {};

    for (int kc = 0; kc < H_; kc += 32) {
        __syncthreads();
        // A tile 128x32: 512 tasks (row, 8-col group), 2 per thread
        #pragma unroll
        for (int p = 0; p < 2; p++) {
            int t   = tid + p * 256;
            int row = t >> 2;
            int k8  = (t & 3) * 8;
            const float* src = &x[(size_t)(m0 + row) * H_ + kc + k8];
            float4 v0 = *(const float4*)src;
            float4 v1 = *(const float4*)(src + 4);
            PERM_STORE(&As[row * APITCH + k8], v0, v1);
        }
        // B tile 64x32: 256 tasks, 1 per thread
        {
            int row = tid >> 2;
            int k8  = (tid & 3) * 8;
            const float* src = &WT[(size_t)row * H_ + kc + k8];
            float4 v0 = *(const float4*)src;
            float4 v1 = *(const float4*)(src + 4);
            PERM_STORE(&Bs[row * APITCH + k8], v0, v1);
        }
        __syncthreads();

        #pragma unroll
        for (int k0 = 0; k0 < 32; k0 += 8) {
            float2 aL[2], aH[2];
            #pragma unroll
            for (int ma = 0; ma < 2; ma++) {
                int r = m0w + ma * 16 + g;
                aL[ma] = *(float2*)&As[r * APITCH + k0 + 2 * c];
                aH[ma] = *(float2*)&As[(r + 8) * APITCH + k0 + 2 * c];
            }
            #pragma unroll
            for (int na = 0; na < 4; na++) {
                float2 b = *(float2*)&Bs[(n0w + na * 8 + g) * APITCH + k0 + 2 * c];
                #pragma unroll
                for (int ma = 0; ma < 2; ma++)
                    mma_tf32(Cf[ma][na], aL[ma].x, aH[ma].x, aL[ma].y, aH[ma].y,
                             b.x, b.y);
            }
        }
    }

    const float scale = (qkv == 0) ? SCALE_ : 1.0f;
    #pragma unroll
    for (int ma = 0; ma < 2; ma++) {
        #pragma unroll
        for (int na = 0; na < 4; na++) {
            int n = n0w + na * 8 + 2 * c;
            float b0 = bias[n], b1 = bias[n + 1];
            #pragma unroll
            for (int half = 0; half < 2; half++) {
                int m = m0 + m0w + ma * 16 + g + half * 8;
                int bb = m >> 11;
                int s  = m & (S_ - 1);
                size_t base = (((size_t)bb * NH_ + h) * S_ + s) * D_ + n;
                float2 o;
                o.x = (Cf[ma][na][half * 2 + 0] + b0) * scale;
                o.y = (Cf[ma][na][half * 2 + 1] + b1) * scale;
                *(float2*)&out[base] = o;
            }
        }
    }
}

// ---------------------------------------------------------------------------
// Flash attention with tf32 mma. grid (16, 48), 256 thr (8 warps).
// Block: 128 q-rows; k-tiles of 64. Warp: 16 q-rows x full 64-key width.
// All smem in permuted-pair layout, pitch 72 (72 % 32 == 8).
// ---------------------------------------------------------------------------
#define QPITCH 72
__global__ __launch_bounds__(256, 2) void attn_tc(float* __restrict__ out)
{
    const int bh = blockIdx.y;
    const int bb = bh / NH_;
    const int h  = bh % NH_;
    const int q0 = blockIdx.x * 128;

    extern __shared__ float sm[];
    float* Qs = sm;                    // [128][QPITCH]  (q, d)
    float* Ks = Qs + 128 * QPITCH;     // [64][QPITCH]   (key, d)
    float* Vt = Ks + 64 * QPITCH;      // [64][QPITCH]   (d, key)
    float* Ps = Vt + 64 * QPITCH;      // [128][QPITCH]  (q, key)

    const float* Qg  = g_Q  + (size_t)bh * S_ * D_;
    const float* Kg  = g_K  + (size_t)bh * S_ * D_;
    const float* VTg = g_VT + (size_t)bh * D_ * S_;

    const int tid  = threadIdx.x;
    const int w    = tid >> 5;
    const int lane = tid & 31;
    const int g    = lane >> 2;
    const int c    = lane & 3;
    const int m0   = w * 16;          // warp's q-row offset within block
    // P-staging positions for logical cols 2c and 2c+1 within an 8-col group
    const int pp0 = ((2 * c) & 3) * 2 + ((2 * c) >> 2);
    const int pp1 = ((2 * c + 1) & 3) * 2 + ((2 * c + 1) >> 2);

    // Row bases (floats) used every k-step
    const int rA0 = (m0 + g) * QPITCH;
    const int rA1 = (m0 + g + 8) * QPITCH;

    // Load Q tile 128x64: 1024 tasks (row, 8-col group), 4 per thread
    #pragma unroll
    for (int p = 0; p < 4; p++) {
        int t   = tid + p * 256;
        int row = t >> 3;
        int k8  = (t & 7) * 8;
        const float* src = &Qg[(size_t)(q0 + row) * D_ + k8];
        float4 v0 = *(const float4*)src;
        float4 v1 = *(const float4*)(src + 4);
        PERM_STORE(&Qs[row * QPITCH + k8], v0, v1);
    }

    float m_i[2] = {-INFINITY, -INFINITY};
    float l_i[2] = {0.0f, 0.0f};
    float O[8][4] = {};

    for (int kt = 0; kt < S_; kt += 64) {
        __syncthreads();   // previous tile fully consumed (covers Q fill on iter 0)
        // K tile 64x64 and V^T tile 64x64: 512 tasks each, 2 per thread
        #pragma unroll
        for (int p = 0; p < 2; p++) {
            int t   = tid + p * 256;
            int row = t >> 3;
            int k8  = (t & 7) * 8;
            const float* srcK = &Kg[(size_t)(kt + row) * D_ + k8];
            float4 k0v = *(const float4*)srcK;
            float4 k1v = *(const float4*)(srcK + 4);
            PERM_STORE(&Ks[row * QPITCH + k8], k0v, k1v);
            const float* srcV = &VTg[(size_t)row * S_ + kt + k8];
            float4 v0v = *(const float4*)srcV;
            float4 v1v = *(const float4*)(srcV + 4);
            PERM_STORE(&Vt[row * QPITCH + k8], v0v, v1v);
        }
        __syncthreads();

        // S = Q K^T : warp computes rows [m0, m0+16) x 64 keys
        float Sf[8][4] = {};
        #pragma unroll
        for (int k0 = 0; k0 < 64; k0 += 8) {
            float2 aL = *(float2*)&Qs[rA0 + k0 + 2 * c];
            float2 aH = *(float2*)&Qs[rA1 + k0 + 2 * c];
            #pragma unroll
            for (int na = 0; na < 8; na++) {
                float2 b = *(float2*)&Ks[(na * 8 + g) * QPITCH + k0 + 2 * c];
                mma_tf32(Sf[na], aL.x, aH.x, aL.y, aH.y, b.x, b.y);
            }
        }

        // Online softmax. Thread owns rows (m0+g) [regs 0,1] and (m0+g+8) [2,3].
        #pragma unroll
        for (int half = 0; half < 2; half++) {
            float mx = -INFINITY;
            #pragma unroll
            for (int na = 0; na < 8; na++)
                mx = fmaxf(mx, fmaxf(Sf[na][half * 2], Sf[na][half * 2 + 1]));
            mx = fmaxf(mx, __shfl_xor_sync(0xffffffffu, mx, 1));
            mx = fmaxf(mx, __shfl_xor_sync(0xffffffffu, mx, 2));
            float mnew  = fmaxf(m_i[half], mx);
            float alpha = __expf(m_i[half] - mnew);
            m_i[half] = mnew;
            float rs = 0.0f;
            #pragma unroll
            for (int na = 0; na < 8; na++) {
                float p0 = __expf(Sf[na][half * 2]     - mnew);
                float p1 = __expf(Sf[na][half * 2 + 1] - mnew);
                Sf[na][half * 2]     = p0;
                Sf[na][half * 2 + 1] = p1;
                rs += p0 + p1;
            }
            rs += __shfl_xor_sync(0xffffffffu, rs, 1);
            rs += __shfl_xor_sync(0xffffffffu, rs, 2);
            l_i[half] = l_i[half] * alpha + rs;
            #pragma unroll
            for (int na = 0; na < 8; na++) {
                O[na][half * 2]     *= alpha;
                O[na][half * 2 + 1] *= alpha;
            }
        }

        // Stage P (tf32-rounded) into permuted layout, warp-private rows
        #pragma unroll
        for (int na = 0; na < 8; na++) {
            float* pr0 = &Ps[rA0 + na * 8];
            pr0[pp0] = tf(Sf[na][0]);
            pr0[pp1] = tf(Sf[na][1]);
            float* pr1 = &Ps[rA1 + na * 8];
            pr1[pp0] = tf(Sf[na][2]);
            pr1[pp1] = tf(Sf[na][3]);
        }
        __syncwarp();

        // O += P V : A = Ps (warp rows, k=keys), B = Vt (n=d, k=keys)
        #pragma unroll
        for (int k0 = 0; k0 < 64; k0 += 8) {
            float2 aL = *(float2*)&Ps[rA0 + k0 + 2 * c];
            float2 aH = *(float2*)&Ps[rA1 + k0 + 2 * c];
            #pragma unroll
            for (int na = 0; na < 8; na++) {
                float2 b = *(float2*)&Vt[(na * 8 + g) * QPITCH + k0 + 2 * c];
                mma_tf32(O[na], aL.x, aH.x, aL.y, aH.y, b.x, b.y);
            }
        }
    }

    // Epilogue: normalize and write out[b][s][h*64+d]
    float inv0 = 1.0f / l_i[0];
    float inv1 = 1.0f / l_i[1];
    #pragma unroll
    for (int na = 0; na < 8; na++) {
        int d0 = na * 8 + 2 * c;
        int r0 = q0 + m0 + g;
        size_t base0 = ((size_t)bb * S_ + r0) * (NH_ * D_) + h * D_ + d0;
        float2 o0; o0.x = O[na][0] * inv0; o0.y = O[na][1] * inv0;
        *(float2*)&out[base0] = o0;
        size_t base1 = ((size_t)bb * S_ + r0 + 8) * (NH_ * D_) + h * D_ + d0;
        float2 o1; o1.x = O[na][2] * inv1; o1.y = O[na][3] * inv1;
        *(float2*)&out[base1] = o1;
    }
}

// ---------------------------------------------------------------------------
extern "C" void kernel_launch(void* const* d_in, const int* in_sizes, int n_in,
                              void* d_out, int out_size)
{
    const float* e1 = (const float*)d_in[0];
    const float* e2 = (const float*)d_in[1];
    const float* e3 = (const float*)d_in[2];
    const float* Wq = (const float*)d_in[3];
    const float* bq = (const float*)d_in[4];
    const float* Wk = (const float*)d_in[5];
    const float* bk = (const float*)d_in[6];
    const float* Wv = (const float*)d_in[7];
    const float* bv = (const float*)d_in[8];
    float* out = (float*)d_out;

    const int attn_smem = 384 * QPITCH * sizeof(float);   // 110592 B
    static bool attr_set = false;
    if (!attr_set) {
        cudaFuncSetAttribute(attn_tc, cudaFuncAttributeMaxDynamicSharedMemorySize,
                             attn_smem);
        attr_set = true;
    }

    transpose_W<<<dim3(48, 36), 256>>>(Wq, Wk, Wv);
    qkv_proj_tc<<<dim3((B_ * S_) / 128, 36), 256>>>(e1, e2, e3, bq, bk, bv);
    transpose_V<<<dim3(128, B_ * NH_), 256>>>();
    attn_tc<<<dim3(S_ / 128, B_ * NH_), 256, attn_smem>>>(out);
}

// round 4
// speedup vs baseline: 1.1908x; 1.1908x over previous
#include <cuda_runtime.h>
#include <math.h>
#include <stdint.h>

#define B_  4
#define S_  2048
#define H_  768
#define NH_ 12
#define D_  64
#define SCALE_ 0.125f   // 1/sqrt(64)

// Scratch, layout [b][h][s][d]
__device__ float g_Q[(size_t)B_ * NH_ * S_ * D_];
__device__ float g_K[(size_t)B_ * NH_ * S_ * D_];
__device__ float g_V[(size_t)B_ * NH_ * S_ * D_];
// Transposed weights [qkv][h][d][H]  and V [b][h][d][s]
__device__ float g_WT[(size_t)3 * NH_ * D_ * H_];
__device__ float g_VT[(size_t)B_ * NH_ * D_ * S_];

// ---------------------------------------------------------------------------
__device__ __forceinline__ uint32_t f2tf32(float f) {
    uint32_t u;
    asm("cvt.rna.tf32.f32 %0, %1;" : "=r"(u) : "f"(f));
    return u;
}
__device__ __forceinline__ void mma_tf32(float c[4], uint32_t a0, uint32_t a1,
                                         uint32_t a2, uint32_t a3,
                                         uint32_t b0, uint32_t b1) {
    asm volatile(
        "mma.sync.aligned.m16n8k8.row.col.f32.tf32.tf32.f32 "
        "{%0,%1,%2,%3}, {%4,%5,%6,%7}, {%8,%9}, {%0,%1,%2,%3};"
        : "+f"(c[0]), "+f"(c[1]), "+f"(c[2]), "+f"(c[3])
        : "r"(a0), "r"(a1), "r"(a2), "r"(a3), "r"(b0), "r"(b1));
}

// ---------------------------------------------------------------------------
// Transpose W[h][H][D] -> g_WT[qkv][h][D][H]. grid (48, 36), 256 thr.
// ---------------------------------------------------------------------------
__global__ __launch_bounds__(256) void transpose_W(
    const float* __restrict__ Wq, const float* __restrict__ Wk,
    const float* __restrict__ Wv)
{
    const int qkv = blockIdx.y / NH_;
    const int h   = blockIdx.y % NH_;
    const float* W = (qkv == 0 ? Wq : (qkv == 1 ? Wk : Wv)) + (size_t)h * H_ * D_;
    float* WT = g_WT + (size_t)blockIdx.y * D_ * H_;

    const int kt = (blockIdx.x >> 1) * 32;   // k-tile (H dim)
    const int nt = (blockIdx.x & 1) * 32;    // n-tile (D dim)

    __shared__ float t[32][33];
    const int r  = threadIdx.x >> 3;          // 0..31
    const int c4 = (threadIdx.x & 7) * 4;     // 0,4,..28

    float4 v = *(const float4*)&W[(size_t)(kt + r) * D_ + nt + c4];
    t[r][c4 + 0] = v.x; t[r][c4 + 1] = v.y; t[r][c4 + 2] = v.z; t[r][c4 + 3] = v.w;
    __syncthreads();
    float4 o;
    o.x = t[c4 + 0][r]; o.y = t[c4 + 1][r]; o.z = t[c4 + 2][r]; o.w = t[c4 + 3][r];
    *(float4*)&WT[(size_t)(nt + r) * H_ + kt + c4] = o;
}

// ---------------------------------------------------------------------------
// Transpose g_V[bh][S][D] -> g_VT[bh][D][S]. grid (128, 48), 256 thr.
// ---------------------------------------------------------------------------
__global__ __launch_bounds__(256) void transpose_V()
{
    const int bh = blockIdx.y;
    const float* V = g_V + (size_t)bh * S_ * D_;
    float* VT = g_VT + (size_t)bh * D_ * S_;

    const int st = (blockIdx.x >> 1) * 32;   // seq tile
    const int dt = (blockIdx.x & 1) * 32;    // d tile

    __shared__ float t[32][33];
    const int r  = threadIdx.x >> 3;
    const int c4 = (threadIdx.x & 7) * 4;

    float4 v = *(const float4*)&V[(size_t)(st + r) * D_ + dt + c4];
    t[r][c4 + 0] = v.x; t[r][c4 + 1] = v.y; t[r][c4 + 2] = v.z; t[r][c4 + 3] = v.w;
    __syncthreads();
    float4 o;
    o.x = t[c4 + 0][r]; o.y = t[c4 + 1][r]; o.z = t[c4 + 2][r]; o.w = t[c4 + 3][r];
    *(float4*)&VT[(size_t)(dt + r) * S_ + st + c4] = o;
}

// ---------------------------------------------------------------------------
// QKV projection with tf32 mma (R1 version). grid (64, 36), 256 thr (8 warps).
// Block tile: 128 rows x 64 cols. Warp tile: 32x32 (2 m-atoms x 4 n-atoms).
// ---------------------------------------------------------------------------
#define APITCH 36   // 36 % 32 == 4 -> conflict-free fragment loads
__global__ __launch_bounds__(256, 2) void qkv_proj_tc(
    const float* __restrict__ e1, const float* __restrict__ e2,
    const float* __restrict__ e3,
    const float* __restrict__ bq, const float* __restrict__ bk,
    const float* __restrict__ bv)
{
    const int h   = blockIdx.y % NH_;
    const int qkv = blockIdx.y / NH_;
    const int grp = h >> 2;

    const float* WT   = g_WT + (size_t)blockIdx.y * D_ * H_;    // [D][H]
    const float* bias = (qkv == 0 ? bq : (qkv == 1 ? bk : bv)) + (size_t)h * D_;
    float*       out  = (qkv == 0 ? g_Q : (qkv == 1 ? g_K : g_V));
    const float* x    = (grp == 0 ? e1 : (grp == 1 ? e2 : e3));

    const int m0  = blockIdx.x * 128;
    const int tid = threadIdx.x;
    const int w    = tid >> 5;
    const int lane = tid & 31;
    const int g    = lane >> 2;
    const int c    = lane & 3;
    const int m0w  = (w >> 1) * 32;   // warp row offset
    const int n0w  = (w & 1) * 32;    // warp col offset

    __shared__ float As[128 * APITCH];   // [row][k]
    __shared__ float Bs[64  * APITCH];   // [n=d][k]

    float Cf[2][4][4] = {};

    for (int kc = 0; kc < H_; kc += 32) {
        __syncthreads();
        // A tile 128x32 (1024 float4 -> 4/thread)
        #pragma unroll
        for (int p = 0; p < 4; p++) {
            int idx = tid + p * 256;
            int row = idx >> 3;
            int k4  = (idx & 7) * 4;
            float4 v = *(const float4*)&x[(size_t)(m0 + row) * H_ + kc + k4];
            float* d = &As[row * APITCH + k4];
            d[0] = __uint_as_float(f2tf32(v.x));
            d[1] = __uint_as_float(f2tf32(v.y));
            d[2] = __uint_as_float(f2tf32(v.z));
            d[3] = __uint_as_float(f2tf32(v.w));
        }
        // B tile 64x32 from WT (512 float4 -> 2/thread)
        #pragma unroll
        for (int p = 0; p < 2; p++) {
            int idx = tid + p * 256;
            int n   = idx >> 3;
            int k4  = (idx & 7) * 4;
            float4 v = *(const float4*)&WT[(size_t)n * H_ + kc + k4];
            float* d = &Bs[n * APITCH + k4];
            d[0] = __uint_as_float(f2tf32(v.x));
            d[1] = __uint_as_float(f2tf32(v.y));
            d[2] = __uint_as_float(f2tf32(v.z));
            d[3] = __uint_as_float(f2tf32(v.w));
        }
        __syncthreads();

        #pragma unroll
        for (int k0 = 0; k0 < 32; k0 += 8) {
            uint32_t a[2][4], b[4][2];
            #pragma unroll
            for (int ma = 0; ma < 2; ma++) {
                int r = m0w + ma * 16 + g;
                a[ma][0] = __float_as_uint(As[r * APITCH + k0 + c]);
                a[ma][1] = __float_as_uint(As[(r + 8) * APITCH + k0 + c]);
                a[ma][2] = __float_as_uint(As[r * APITCH + k0 + c + 4]);
                a[ma][3] = __float_as_uint(As[(r + 8) * APITCH + k0 + c + 4]);
            }
            #pragma unroll
            for (int na = 0; na < 4; na++) {
                int n = n0w + na * 8 + g;
                b[na][0] = __float_as_uint(Bs[n * APITCH + k0 + c]);
                b[na][1] = __float_as_uint(Bs[n * APITCH + k0 + c + 4]);
            }
            #pragma unroll
            for (int ma = 0; ma < 2; ma++)
                #pragma unroll
                for (int na = 0; na < 4; na++)
                    mma_tf32(Cf[ma][na], a[ma][0], a[ma][1], a[ma][2], a[ma][3],
                             b[na][0], b[na][1]);
        }
    }

    const float scale = (qkv == 0) ? SCALE_ : 1.0f;
    #pragma unroll
    for (int ma = 0; ma < 2; ma++) {
        #pragma unroll
        for (int na = 0; na < 4; na++) {
            int n = n0w + na * 8 + 2 * c;
            float b0 = bias[n], b1 = bias[n + 1];
            #pragma unroll
            for (int half = 0; half < 2; half++) {
                int m = m0 + m0w + ma * 16 + g + half * 8;
                int bb = m >> 11;
                int s  = m & (S_ - 1);
                size_t base = (((size_t)bb * NH_ + h) * S_ + s) * D_ + n;
                float2 o;
                o.x = (Cf[ma][na][half * 2 + 0] + b0) * scale;
                o.y = (Cf[ma][na][half * 2 + 1] + b1) * scale;
                *(float2*)&out[base] = o;
            }
        }
    }
}

// ---------------------------------------------------------------------------
// Flash attention with tf32 mma. grid (16, 48), 128 thr (4 warps).
// Block: 128 q-rows; k-tiles of 64. Warp: 32 q-rows (2 m-atoms) x 64 keys.
// R1-proven smem layout: pitch 68, scalar fragment loads.
// ---------------------------------------------------------------------------
#define PITCH 68    // 68 % 32 == 4 -> conflict-free fragment loads
__global__ __launch_bounds__(128) void attn_tc(float* __restrict__ out)
{
    const int bh = blockIdx.y;
    const int bb = bh / NH_;
    const int h  = bh % NH_;
    const int q0 = blockIdx.x * 128;

    extern __shared__ float sm[];
    float* Qs = sm;                  // [128][PITCH]  (q, d)
    float* Ks = Qs + 128 * PITCH;    // [64][PITCH]   (key, d)
    float* Vt = Ks + 64 * PITCH;     // [64][PITCH]   (d, key)
    float* Ps = Vt + 64 * PITCH;     // [128][PITCH]  (q, key)

    const float* Qg  = g_Q  + (size_t)bh * S_ * D_;
    const float* Kg  = g_K  + (size_t)bh * S_ * D_;
    const float* VTg = g_VT + (size_t)bh * D_ * S_;

    const int tid  = threadIdx.x;
    const int w    = tid >> 5;
    const int lane = tid & 31;
    const int g    = lane >> 2;
    const int c    = lane & 3;
    const int m0   = w * 32;       // warp's q-row offset within block (2 m-atoms)

    // Load Q tile 128x64 (2048 float4 -> 16/thread), tf32-rounded
    #pragma unroll
    for (int p = 0; p < 16; p++) {
        int idx = tid + p * 128;
        int row = idx >> 4;
        int c4  = (idx & 15) * 4;
        float4 v = *(const float4*)&Qg[(size_t)(q0 + row) * D_ + c4];
        float* d = &Qs[row * PITCH + c4];
        d[0] = __uint_as_float(f2tf32(v.x));
        d[1] = __uint_as_float(f2tf32(v.y));
        d[2] = __uint_as_float(f2tf32(v.z));
        d[3] = __uint_as_float(f2tf32(v.w));
    }

    float m_i[2][2], l_i[2][2];
    #pragma unroll
    for (int ma = 0; ma < 2; ma++)
        #pragma unroll
        for (int hf = 0; hf < 2; hf++) { m_i[ma][hf] = -INFINITY; l_i[ma][hf] = 0.0f; }
    float O[2][8][4] = {};

    for (int kt = 0; kt < S_; kt += 64) {
        __syncthreads();   // previous tile fully consumed (covers Q fill on iter 0)
        // K tile 64x64 and V^T tile 64x64 (1024 float4 each -> 8/thread each)
        #pragma unroll
        for (int p = 0; p < 8; p++) {
            int idx = tid + p * 128;
            int row = idx >> 4;
            int c4  = (idx & 15) * 4;
            float4 kv = *(const float4*)&Kg[(size_t)(kt + row) * D_ + c4];
            float* dk = &Ks[row * PITCH + c4];
            dk[0] = __uint_as_float(f2tf32(kv.x));
            dk[1] = __uint_as_float(f2tf32(kv.y));
            dk[2] = __uint_as_float(f2tf32(kv.z));
            dk[3] = __uint_as_float(f2tf32(kv.w));
            float4 vv = *(const float4*)&VTg[(size_t)row * S_ + kt + c4];
            float* dv = &Vt[row * PITCH + c4];
            dv[0] = __uint_as_float(f2tf32(vv.x));
            dv[1] = __uint_as_float(f2tf32(vv.y));
            dv[2] = __uint_as_float(f2tf32(vv.z));
            dv[3] = __uint_as_float(f2tf32(vv.w));
        }
        __syncthreads();

        // S = Q K^T : warp computes rows [m0, m0+32) x 64 keys
        float Sf[2][8][4] = {};
        #pragma unroll
        for (int k0 = 0; k0 < 64; k0 += 8) {
            uint32_t a[2][4];
            #pragma unroll
            for (int ma = 0; ma < 2; ma++) {
                int r = m0 + ma * 16 + g;
                a[ma][0] = __float_as_uint(Qs[r * PITCH + k0 + c]);
                a[ma][1] = __float_as_uint(Qs[(r + 8) * PITCH + k0 + c]);
                a[ma][2] = __float_as_uint(Qs[r * PITCH + k0 + c + 4]);
                a[ma][3] = __float_as_uint(Qs[(r + 8) * PITCH + k0 + c + 4]);
            }
            #pragma unroll
            for (int na = 0; na < 8; na++) {
                uint32_t b0 = __float_as_uint(Ks[(na * 8 + g) * PITCH + k0 + c]);
                uint32_t b1 = __float_as_uint(Ks[(na * 8 + g) * PITCH + k0 + c + 4]);
                #pragma unroll
                for (int ma = 0; ma < 2; ma++)
                    mma_tf32(Sf[ma][na], a[ma][0], a[ma][1], a[ma][2], a[ma][3],
                             b0, b1);
            }
        }

        // Online softmax. Thread owns rows m0+ma*16+g (+8) per ma.
        #pragma unroll
        for (int ma = 0; ma < 2; ma++) {
            #pragma unroll
            for (int hf = 0; hf < 2; hf++) {
                float mx = -INFINITY;
                #pragma unroll
                for (int na = 0; na < 8; na++)
                    mx = fmaxf(mx, fmaxf(Sf[ma][na][hf * 2], Sf[ma][na][hf * 2 + 1]));
                mx = fmaxf(mx, __shfl_xor_sync(0xffffffffu, mx, 1));
                mx = fmaxf(mx, __shfl_xor_sync(0xffffffffu, mx, 2));
                float mnew  = fmaxf(m_i[ma][hf], mx);
                float alpha = __expf(m_i[ma][hf] - mnew);
                m_i[ma][hf] = mnew;
                float rs = 0.0f;
                #pragma unroll
                for (int na = 0; na < 8; na++) {
                    float p0 = __expf(Sf[ma][na][hf * 2]     - mnew);
                    float p1 = __expf(Sf[ma][na][hf * 2 + 1] - mnew);
                    Sf[ma][na][hf * 2]     = p0;
                    Sf[ma][na][hf * 2 + 1] = p1;
                    rs += p0 + p1;
                }
                rs += __shfl_xor_sync(0xffffffffu, rs, 1);
                rs += __shfl_xor_sync(0xffffffffu, rs, 2);
                l_i[ma][hf] = l_i[ma][hf] * alpha + rs;
                #pragma unroll
                for (int na = 0; na < 8; na++) {
                    O[ma][na][hf * 2]     *= alpha;
                    O[ma][na][hf * 2 + 1] *= alpha;
                }
            }
        }

        // Stage P (tf32-rounded) to warp-private smem rows
        #pragma unroll
        for (int ma = 0; ma < 2; ma++) {
            int r = m0 + ma * 16 + g;
            #pragma unroll
            for (int na = 0; na < 8; na++) {
                float2 p0, p1;
                p0.x = __uint_as_float(f2tf32(Sf[ma][na][0]));
                p0.y = __uint_as_float(f2tf32(Sf[ma][na][1]));
                p1.x = __uint_as_float(f2tf32(Sf[ma][na][2]));
                p1.y = __uint_as_float(f2tf32(Sf[ma][na][3]));
                *(float2*)&Ps[r * PITCH + na * 8 + 2 * c]       = p0;
                *(float2*)&Ps[(r + 8) * PITCH + na * 8 + 2 * c] = p1;
            }
        }
        __syncwarp();

        // O += P V : A = Ps (warp rows, k=keys), B = Vt (n=d, k=keys)
        #pragma unroll
        for (int k0 = 0; k0 < 64; k0 += 8) {
            uint32_t a[2][4];
            #pragma unroll
            for (int ma = 0; ma < 2; ma++) {
                int r = m0 + ma * 16 + g;
                a[ma][0] = __float_as_uint(Ps[r * PITCH + k0 + c]);
                a[ma][1] = __float_as_uint(Ps[(r + 8) * PITCH + k0 + c]);
                a[ma][2] = __float_as_uint(Ps[r * PITCH + k0 + c + 4]);
                a[ma][3] = __float_as_uint(Ps[(r + 8) * PITCH + k0 + c + 4]);
            }
            #pragma unroll
            for (int na = 0; na < 8; na++) {
                uint32_t b0 = __float_as_uint(Vt[(na * 8 + g) * PITCH + k0 + c]);
                uint32_t b1 = __float_as_uint(Vt[(na * 8 + g) * PITCH + k0 + c + 4]);
                #pragma unroll
                for (int ma = 0; ma < 2; ma++)
                    mma_tf32(O[ma][na], a[ma][0], a[ma][1], a[ma][2], a[ma][3],
                             b0, b1);
            }
        }
    }

    // Epilogue: normalize and write out[b][s][h*64+d]
    #pragma unroll
    for (int ma = 0; ma < 2; ma++) {
        float inv0 = 1.0f / l_i[ma][0];
        float inv1 = 1.0f / l_i[ma][1];
        int r0 = q0 + m0 + ma * 16 + g;
        #pragma unroll
        for (int na = 0; na < 8; na++) {
            int d0 = na * 8 + 2 * c;
            size_t base0 = ((size_t)bb * S_ + r0) * (NH_ * D_) + h * D_ + d0;
            float2 o0; o0.x = O[ma][na][0] * inv0; o0.y = O[ma][na][1] * inv0;
            *(float2*)&out[base0] = o0;
            size_t base1 = ((size_t)bb * S_ + r0 + 8) * (NH_ * D_) + h * D_ + d0;
            float2 o1; o1.x = O[ma][na][2] * inv1; o1.y = O[ma][na][3] * inv1;
            *(float2*)&out[base1] = o1;
        }
    }
}

// ---------------------------------------------------------------------------
extern "C" void kernel_launch(void* const* d_in, const int* in_sizes, int n_in,
                              void* d_out, int out_size)
{
    const float* e1 = (const float*)d_in[0];
    const float* e2 = (const float*)d_in[1];
    const float* e3 = (const float*)d_in[2];
    const float* Wq = (const float*)d_in[3];
    const float* bq = (const float*)d_in[4];
    const float* Wk = (const float*)d_in[5];
    const float* bk = (const float*)d_in[6];
    const float* Wv = (const float*)d_in[7];
    const float* bv = (const float*)d_in[8];
    float* out = (float*)d_out;

    const int attn_smem = 384 * PITCH * sizeof(float);   // 104448 B
    static bool attr_set = false;
    if (!attr_set) {
        cudaFuncSetAttribute(attn_tc, cudaFuncAttributeMaxDynamicSharedMemorySize,
                             attn_smem);
        attr_set = true;
    }

    transpose_W<<<dim3(48, 36), 256>>>(Wq, Wk, Wv);
    qkv_proj_tc<<<dim3((B_ * S_) / 128, 36), 256>>>(e1, e2, e3, bq, bk, bv);
    transpose_V<<<dim3(128, B_ * NH_), 256>>>();
    attn_tc<<<dim3(S_ / 128, B_ * NH_), 128, attn_smem>>>(out);
}

// round 5
// speedup vs baseline: 1.2351x; 1.0372x over previous
#include <cuda_runtime.h>
#include <math.h>
#include <stdint.h>

#define B_  4
#define S_  2048
#define H_  768
#define NH_ 12
#define D_  64
#define SCALE_ 0.125f   // 1/sqrt(64)

// Scratch, layout [b][h][s][d]
__device__ float g_Q[(size_t)B_ * NH_ * S_ * D_];
__device__ float g_K[(size_t)B_ * NH_ * S_ * D_];
__device__ float g_V[(size_t)B_ * NH_ * S_ * D_];
// Transposed weights [qkv][h][d][H]  and V [b][h][d][s]
__device__ float g_WT[(size_t)3 * NH_ * D_ * H_];
__device__ float g_VT[(size_t)B_ * NH_ * D_ * S_];

// ---------------------------------------------------------------------------
__device__ __forceinline__ uint32_t f2tf32(float f) {
    uint32_t u;
    asm("cvt.rna.tf32.f32 %0, %1;" : "=r"(u) : "f"(f));
    return u;
}
__device__ __forceinline__ void mma_tf32(float c[4], uint32_t a0, uint32_t a1,
                                         uint32_t a2, uint32_t a3,
                                         uint32_t b0, uint32_t b1) {
    asm volatile(
        "mma.sync.aligned.m16n8k8.row.col.f32.tf32.tf32.f32 "
        "{%0,%1,%2,%3}, {%4,%5,%6,%7}, {%8,%9}, {%0,%1,%2,%3};"
        : "+f"(c[0]), "+f"(c[1]), "+f"(c[2]), "+f"(c[3])
        : "r"(a0), "r"(a1), "r"(a2), "r"(a3), "r"(b0), "r"(b1));
}
// One ldmatrix.x4: 4 m8n8(b16) tiles = 4 fragment registers.
__device__ __forceinline__ void ldsm_x4(uint32_t r[4], uint32_t addr) {
    asm volatile(
        "ldmatrix.sync.aligned.m8n8.x4.shared.b16 {%0,%1,%2,%3}, [%4];"
        : "=r"(r[0]), "=r"(r[1]), "=r"(r[2]), "=r"(r[3]) : "r"(addr));
}

// ---------------------------------------------------------------------------
// Transpose W[h][H][D] -> g_WT[qkv][h][D][H]. grid (48, 36), 256 thr.
// ---------------------------------------------------------------------------
__global__ __launch_bounds__(256) void transpose_W(
    const float* __restrict__ Wq, const float* __restrict__ Wk,
    const float* __restrict__ Wv)
{
    const int qkv = blockIdx.y / NH_;
    const int h   = blockIdx.y % NH_;
    const float* W = (qkv == 0 ? Wq : (qkv == 1 ? Wk : Wv)) + (size_t)h * H_ * D_;
    float* WT = g_WT + (size_t)blockIdx.y * D_ * H_;

    const int kt = (blockIdx.x >> 1) * 32;   // k-tile (H dim)
    const int nt = (blockIdx.x & 1) * 32;    // n-tile (D dim)

    __shared__ float t[32][33];
    const int r  = threadIdx.x >> 3;          // 0..31
    const int c4 = (threadIdx.x & 7) * 4;     // 0,4,..28

    float4 v = *(const float4*)&W[(size_t)(kt + r) * D_ + nt + c4];
    t[r][c4 + 0] = v.x; t[r][c4 + 1] = v.y; t[r][c4 + 2] = v.z; t[r][c4 + 3] = v.w;
    __syncthreads();
    float4 o;
    o.x = t[c4 + 0][r]; o.y = t[c4 + 1][r]; o.z = t[c4 + 2][r]; o.w = t[c4 + 3][r];
    *(float4*)&WT[(size_t)(nt + r) * H_ + kt + c4] = o;
}

// ---------------------------------------------------------------------------
// Transpose g_V[bh][S][D] -> g_VT[bh][D][S]. grid (128, 48), 256 thr.
// ---------------------------------------------------------------------------
__global__ __launch_bounds__(256) void transpose_V()
{
    const int bh = blockIdx.y;
    const float* V = g_V + (size_t)bh * S_ * D_;
    float* VT = g_VT + (size_t)bh * D_ * S_;

    const int st = (blockIdx.x >> 1) * 32;   // seq tile
    const int dt = (blockIdx.x & 1) * 32;    // d tile

    __shared__ float t[32][33];
    const int r  = threadIdx.x >> 3;
    const int c4 = (threadIdx.x & 7) * 4;

    float4 v = *(const float4*)&V[(size_t)(st + r) * D_ + dt + c4];
    t[r][c4 + 0] = v.x; t[r][c4 + 1] = v.y; t[r][c4 + 2] = v.z; t[r][c4 + 3] = v.w;
    __syncthreads();
    float4 o;
    o.x = t[c4 + 0][r]; o.y = t[c4 + 1][r]; o.z = t[c4 + 2][r]; o.w = t[c4 + 3][r];
    *(float4*)&VT[(size_t)(dt + r) * S_ + st + c4] = o;
}

// ---------------------------------------------------------------------------
// QKV projection with tf32 mma + ldmatrix. grid (64, 36), 256 thr (8 warps).
// Block tile: 128 rows x 64 cols. Warp tile: 32x32 (2 m-atoms x 4 n-atoms).
// ---------------------------------------------------------------------------
#define APITCH 36   // 36 % 32 == 4; row stride 144B = 9*16B -> LDSM conflict-free
__global__ __launch_bounds__(256, 2) void qkv_proj_tc(
    const float* __restrict__ e1, const float* __restrict__ e2,
    const float* __restrict__ e3,
    const float* __restrict__ bq, const float* __restrict__ bk,
    const float* __restrict__ bv)
{
    const int h   = blockIdx.y % NH_;
    const int qkv = blockIdx.y / NH_;
    const int grp = h >> 2;

    const float* WT   = g_WT + (size_t)blockIdx.y * D_ * H_;    // [D][H]
    const float* bias = (qkv == 0 ? bq : (qkv == 1 ? bk : bv)) + (size_t)h * D_;
    float*       out  = (qkv == 0 ? g_Q : (qkv == 1 ? g_K : g_V));
    const float* x    = (grp == 0 ? e1 : (grp == 1 ? e2 : e3));

    const int m0  = blockIdx.x * 128;
    const int tid = threadIdx.x;
    const int w    = tid >> 5;
    const int lane = tid & 31;
    const int g    = lane >> 2;
    const int c    = lane & 3;
    const int m0w  = (w >> 1) * 32;   // warp row offset
    const int n0w  = (w & 1) * 32;    // warp col offset

    // ldmatrix lane->tile decomposition
    const int mrow = lane & 7;
    const int msel = lane >> 3;               // matrix index 0..3
    const int a_row = (msel & 1) * 8 + mrow;  // A-type: r0=(g,c) r1=(g+8,c) r2=(g,c+4) r3=(g+8,c+4)
    const int a_col = (msel >> 1) * 4;
    const int b_row = (msel >> 1) * 8 + mrow; // B-type: r0,r1 = b0,b1 of na0; r2,r3 of na1
    const int b_col = (msel & 1) * 4;

    __shared__ float As[128 * APITCH];   // [row][k]
    __shared__ float Bs[64  * APITCH];   // [n=d][k]
    const uint32_t AsU = (uint32_t)__cvta_generic_to_shared(As);
    const uint32_t BsU = (uint32_t)__cvta_generic_to_shared(Bs);

    float Cf[2][4][4] = {};

    for (int kc = 0; kc < H_; kc += 32) {
        __syncthreads();
        // A tile 128x32 (1024 float4 -> 4/thread)
        #pragma unroll
        for (int p = 0; p < 4; p++) {
            int idx = tid + p * 256;
            int row = idx >> 3;
            int k4  = (idx & 7) * 4;
            float4 v = *(const float4*)&x[(size_t)(m0 + row) * H_ + kc + k4];
            float* d = &As[row * APITCH + k4];
            d[0] = __uint_as_float(f2tf32(v.x));
            d[1] = __uint_as_float(f2tf32(v.y));
            d[2] = __uint_as_float(f2tf32(v.z));
            d[3] = __uint_as_float(f2tf32(v.w));
        }
        // B tile 64x32 from WT (512 float4 -> 2/thread)
        #pragma unroll
        for (int p = 0; p < 2; p++) {
            int idx = tid + p * 256;
            int n   = idx >> 3;
            int k4  = (idx & 7) * 4;
            float4 v = *(const float4*)&WT[(size_t)n * H_ + kc + k4];
            float* d = &Bs[n * APITCH + k4];
            d[0] = __uint_as_float(f2tf32(v.x));
            d[1] = __uint_as_float(f2tf32(v.y));
            d[2] = __uint_as_float(f2tf32(v.z));
            d[3] = __uint_as_float(f2tf32(v.w));
        }
        __syncthreads();

        #pragma unroll
        for (int k0 = 0; k0 < 32; k0 += 8) {
            uint32_t a[2][4], b[2][4];
            #pragma unroll
            for (int ma = 0; ma < 2; ma++)
                ldsm_x4(a[ma], AsU + (uint32_t)(((m0w + ma * 16 + a_row) * APITCH
                                                 + k0 + a_col) * 4));
            #pragma unroll
            for (int p = 0; p < 2; p++)
                ldsm_x4(b[p], BsU + (uint32_t)(((n0w + p * 16 + b_row) * APITCH
                                                + k0 + b_col) * 4));
            #pragma unroll
            for (int ma = 0; ma < 2; ma++)
                #pragma unroll
                for (int na = 0; na < 4; na++)
                    mma_tf32(Cf[ma][na], a[ma][0], a[ma][1], a[ma][2], a[ma][3],
                             b[na >> 1][(na & 1) * 2], b[na >> 1][(na & 1) * 2 + 1]);
        }
    }

    const float scale = (qkv == 0) ? SCALE_ : 1.0f;
    #pragma unroll
    for (int ma = 0; ma < 2; ma++) {
        #pragma unroll
        for (int na = 0; na < 4; na++) {
            int n = n0w + na * 8 + 2 * c;
            float b0 = bias[n], b1 = bias[n + 1];
            #pragma unroll
            for (int half = 0; half < 2; half++) {
                int m = m0 + m0w + ma * 16 + g + half * 8;
                int bb = m >> 11;
                int s  = m & (S_ - 1);
                size_t base = (((size_t)bb * NH_ + h) * S_ + s) * D_ + n;
                float2 o;
                o.x = (Cf[ma][na][half * 2 + 0] + b0) * scale;
                o.y = (Cf[ma][na][half * 2 + 1] + b1) * scale;
                *(float2*)&out[base] = o;
            }
        }
    }
}

// ---------------------------------------------------------------------------
// Flash attention with tf32 mma + ldmatrix. grid (16, 48), 128 thr (4 warps).
// Block: 128 q-rows; k-tiles of 64. Warp: 32 q-rows (2 m-atoms) x 64 keys.
// ---------------------------------------------------------------------------
#define PITCH 68    // 68 % 32 == 4; row stride 272B = 17*16B -> LDSM conflict-free
__global__ __launch_bounds__(128) void attn_tc(float* __restrict__ out)
{
    const int bh = blockIdx.y;
    const int bb = bh / NH_;
    const int h  = bh % NH_;
    const int q0 = blockIdx.x * 128;

    extern __shared__ float sm[];
    float* Qs = sm;                  // [128][PITCH]  (q, d)
    float* Ks = Qs + 128 * PITCH;    // [64][PITCH]   (key, d)
    float* Vt = Ks + 64 * PITCH;     // [64][PITCH]   (d, key)
    float* Ps = Vt + 64 * PITCH;     // [128][PITCH]  (q, key)
    const uint32_t QsU = (uint32_t)__cvta_generic_to_shared(Qs);
    const uint32_t KsU = (uint32_t)__cvta_generic_to_shared(Ks);
    const uint32_t VtU = (uint32_t)__cvta_generic_to_shared(Vt);
    const uint32_t PsU = (uint32_t)__cvta_generic_to_shared(Ps);

    const float* Qg  = g_Q  + (size_t)bh * S_ * D_;
    const float* Kg  = g_K  + (size_t)bh * S_ * D_;
    const float* VTg = g_VT + (size_t)bh * D_ * S_;

    const int tid  = threadIdx.x;
    const int w    = tid >> 5;
    const int lane = tid & 31;
    const int g    = lane >> 2;
    const int c    = lane & 3;
    const int m0   = w * 32;       // warp's q-row offset within block (2 m-atoms)

    // ldmatrix lane->tile decomposition
    const int mrow = lane & 7;
    const int msel = lane >> 3;
    const int a_row = (msel & 1) * 8 + mrow;
    const int a_col = (msel >> 1) * 4;
    const int b_row = (msel >> 1) * 8 + mrow;
    const int b_col = (msel & 1) * 4;

    // Per-thread LDSM base offsets (in bytes), k0 added per step
    const uint32_t aQ0 = QsU + (uint32_t)(((m0 + a_row) * PITCH + a_col) * 4);
    const uint32_t aQ1 = QsU + (uint32_t)(((m0 + 16 + a_row) * PITCH + a_col) * 4);
    const uint32_t aP0 = PsU + (uint32_t)(((m0 + a_row) * PITCH + a_col) * 4);
    const uint32_t aP1 = PsU + (uint32_t)(((m0 + 16 + a_row) * PITCH + a_col) * 4);

    // Load Q tile 128x64 (2048 float4 -> 16/thread), tf32-rounded
    #pragma unroll
    for (int p = 0; p < 16; p++) {
        int idx = tid + p * 128;
        int row = idx >> 4;
        int c4  = (idx & 15) * 4;
        float4 v = *(const float4*)&Qg[(size_t)(q0 + row) * D_ + c4];
        float* d = &Qs[row * PITCH + c4];
        d[0] = __uint_as_float(f2tf32(v.x));
        d[1] = __uint_as_float(f2tf32(v.y));
        d[2] = __uint_as_float(f2tf32(v.z));
        d[3] = __uint_as_float(f2tf32(v.w));
    }

    float m_i[2][2], l_i[2][2];
    #pragma unroll
    for (int ma = 0; ma < 2; ma++)
        #pragma unroll
        for (int hf = 0; hf < 2; hf++) { m_i[ma][hf] = -INFINITY; l_i[ma][hf] = 0.0f; }
    float O[2][8][4] = {};

    for (int kt = 0; kt < S_; kt += 64) {
        __syncthreads();   // previous tile fully consumed (covers Q fill on iter 0)
        // K tile 64x64 and V^T tile 64x64 (1024 float4 each -> 8/thread each)
        #pragma unroll
        for (int p = 0; p < 8; p++) {
            int idx = tid + p * 128;
            int row = idx >> 4;
            int c4  = (idx & 15) * 4;
            float4 kv = *(const float4*)&Kg[(size_t)(kt + row) * D_ + c4];
            float* dk = &Ks[row * PITCH + c4];
            dk[0] = __uint_as_float(f2tf32(kv.x));
            dk[1] = __uint_as_float(f2tf32(kv.y));
            dk[2] = __uint_as_float(f2tf32(kv.z));
            dk[3] = __uint_as_float(f2tf32(kv.w));
            float4 vv = *(const float4*)&VTg[(size_t)row * S_ + kt + c4];
            float* dv = &Vt[row * PITCH + c4];
            dv[0] = __uint_as_float(f2tf32(vv.x));
            dv[1] = __uint_as_float(f2tf32(vv.y));
            dv[2] = __uint_as_float(f2tf32(vv.z));
            dv[3] = __uint_as_float(f2tf32(vv.w));
        }
        __syncthreads();

        // S = Q K^T : warp computes rows [m0, m0+32) x 64 keys
        float Sf[2][8][4] = {};
        #pragma unroll
        for (int k0 = 0; k0 < 64; k0 += 8) {
            uint32_t a[2][4], b[4][4];
            ldsm_x4(a[0], aQ0 + (uint32_t)(k0 * 4));
            ldsm_x4(a[1], aQ1 + (uint32_t)(k0 * 4));
            #pragma unroll
            for (int p = 0; p < 4; p++)
                ldsm_x4(b[p], KsU + (uint32_t)(((p * 16 + b_row) * PITCH
                                                + k0 + b_col) * 4));
            #pragma unroll
            for (int na = 0; na < 8; na++) {
                uint32_t b0 = b[na >> 1][(na & 1) * 2];
                uint32_t b1 = b[na >> 1][(na & 1) * 2 + 1];
                #pragma unroll
                for (int ma = 0; ma < 2; ma++)
                    mma_tf32(Sf[ma][na], a[ma][0], a[ma][1], a[ma][2], a[ma][3],
                             b0, b1);
            }
        }

        // Online softmax. Thread owns rows m0+ma*16+g (+8) per ma.
        #pragma unroll
        for (int ma = 0; ma < 2; ma++) {
            #pragma unroll
            for (int hf = 0; hf < 2; hf++) {
                float mx = -INFINITY;
                #pragma unroll
                for (int na = 0; na < 8; na++)
                    mx = fmaxf(mx, fmaxf(Sf[ma][na][hf * 2], Sf[ma][na][hf * 2 + 1]));
                mx = fmaxf(mx, __shfl_xor_sync(0xffffffffu, mx, 1));
                mx = fmaxf(mx, __shfl_xor_sync(0xffffffffu, mx, 2));
                float mnew  = fmaxf(m_i[ma][hf], mx);
                float alpha = __expf(m_i[ma][hf] - mnew);
                m_i[ma][hf] = mnew;
                float rs = 0.0f;
                #pragma unroll
                for (int na = 0; na < 8; na++) {
                    float p0 = __expf(Sf[ma][na][hf * 2]     - mnew);
                    float p1 = __expf(Sf[ma][na][hf * 2 + 1] - mnew);
                    Sf[ma][na][hf * 2]     = p0;
                    Sf[ma][na][hf * 2 + 1] = p1;
                    rs += p0 + p1;
                }
                rs += __shfl_xor_sync(0xffffffffu, rs, 1);
                rs += __shfl_xor_sync(0xffffffffu, rs, 2);
                l_i[ma][hf] = l_i[ma][hf] * alpha + rs;
                #pragma unroll
                for (int na = 0; na < 8; na++) {
                    O[ma][na][hf * 2]     *= alpha;
                    O[ma][na][hf * 2 + 1] *= alpha;
                }
            }
        }

        // Stage P (tf32-rounded) to warp-private smem rows
        #pragma unroll
        for (int ma = 0; ma < 2; ma++) {
            int r = m0 + ma * 16 + g;
            #pragma unroll
            for (int na = 0; na < 8; na++) {
                float2 p0, p1;
                p0.x = __uint_as_float(f2tf32(Sf[ma][na][0]));
                p0.y = __uint_as_float(f2tf32(Sf[ma][na][1]));
                p1.x = __uint_as_float(f2tf32(Sf[ma][na][2]));
                p1.y = __uint_as_float(f2tf32(Sf[ma][na][3]));
                *(float2*)&Ps[r * PITCH + na * 8 + 2 * c]       = p0;
                *(float2*)&Ps[(r + 8) * PITCH + na * 8 + 2 * c] = p1;
            }
        }
        __syncwarp();

        // O += P V : A = Ps (warp rows, k=keys), B = Vt (n=d, k=keys)
        #pragma unroll
        for (int k0 = 0; k0 < 64; k0 += 8) {
            uint32_t a[2][4], b[4][4];
            ldsm_x4(a[0], aP0 + (uint32_t)(k0 * 4));
            ldsm_x4(a[1], aP1 + (uint32_t)(k0 * 4));
            #pragma unroll
            for (int p = 0; p < 4; p++)
                ldsm_x4(b[p], VtU + (uint32_t)(((p * 16 + b_row) * PITCH
                                                + k0 + b_col) * 4));
            #pragma unroll
            for (int na = 0; na < 8; na++) {
                uint32_t b0 = b[na >> 1][(na & 1) * 2];
                uint32_t b1 = b[na >> 1][(na & 1) * 2 + 1];
                #pragma unroll
                for (int ma = 0; ma < 2; ma++)
                    mma_tf32(O[ma][na], a[ma][0], a[ma][1], a[ma][2], a[ma][3],
                             b0, b1);
            }
        }
    }

    // Epilogue: normalize and write out[b][s][h*64+d]
    #pragma unroll
    for (int ma = 0; ma < 2; ma++) {
        float inv0 = 1.0f / l_i[ma][0];
        float inv1 = 1.0f / l_i[ma][1];
        int r0 = q0 + m0 + ma * 16 + g;
        #pragma unroll
        for (int na = 0; na < 8; na++) {
            int d0 = na * 8 + 2 * c;
            size_t base0 = ((size_t)bb * S_ + r0) * (NH_ * D_) + h * D_ + d0;
            float2 o0; o0.x = O[ma][na][0] * inv0; o0.y = O[ma][na][1] * inv0;
            *(float2*)&out[base0] = o0;
            size_t base1 = ((size_t)bb * S_ + r0 + 8) * (NH_ * D_) + h * D_ + d0;
            float2 o1; o1.x = O[ma][na][2] * inv1; o1.y = O[ma][na][3] * inv1;
            *(float2*)&out[base1] = o1;
        }
    }
}

// ---------------------------------------------------------------------------
extern "C" void kernel_launch(void* const* d_in, const int* in_sizes, int n_in,
                              void* d_out, int out_size)
{
    const float* e1 = (const float*)d_in[0];
    const float* e2 = (const float*)d_in[1];
    const float* e3 = (const float*)d_in[2];
    const float* Wq = (const float*)d_in[3];
    const float* bq = (const float*)d_in[4];
    const float* Wk = (const float*)d_in[5];
    const float* bk = (const float*)d_in[6];
    const float* Wv = (const float*)d_in[7];
    const float* bv = (const float*)d_in[8];
    float* out = (float*)d_out;

    const int attn_smem = 384 * PITCH * sizeof(float);   // 104448 B
    static bool attr_set = false;
    if (!attr_set) {
        cudaFuncSetAttribute(attn_tc, cudaFuncAttributeMaxDynamicSharedMemorySize,
                             attn_smem);
        attr_set = true;
    }

    transpose_W<<<dim3(48, 36), 256>>>(Wq, Wk, Wv);
    qkv_proj_tc<<<dim3((B_ * S_) / 128, 36), 256>>>(e1, e2, e3, bq, bk, bv);
    transpose_V<<<dim3(128, B_ * NH_), 256>>>();
    attn_tc<<<dim3(S_ / 128, B_ * NH_), 128, attn_smem>>>(out);
}

// round 6
// speedup vs baseline: 1.3399x; 1.0849x over previous
#include <cuda_runtime.h>
#include <math.h>
#include <stdint.h>

#define B_  4
#define S_  2048
#define H_  768
#define NH_ 12
#define D_  64
#define SCALE_ 0.125f   // 1/sqrt(64)

// Scratch, layout [b][h][s][d]
__device__ float g_Q[(size_t)B_ * NH_ * S_ * D_];
__device__ float g_K[(size_t)B_ * NH_ * S_ * D_];
__device__ float g_V[(size_t)B_ * NH_ * S_ * D_];
// Transposed weights [qkv][h][d][H]  and V [b][h][d][s]
__device__ float g_WT[(size_t)3 * NH_ * D_ * H_];
__device__ float g_VT[(size_t)B_ * NH_ * D_ * S_];

// ---------------------------------------------------------------------------
__device__ __forceinline__ uint32_t f2tf32(float f) {
    uint32_t u;
    asm("cvt.rna.tf32.f32 %0, %1;" : "=r"(u) : "f"(f));
    return u;
}
__device__ __forceinline__ void mma_tf32(float c[4], uint32_t a0, uint32_t a1,
                                         uint32_t a2, uint32_t a3,
                                         uint32_t b0, uint32_t b1) {
    asm volatile(
        "mma.sync.aligned.m16n8k8.row.col.f32.tf32.tf32.f32 "
        "{%0,%1,%2,%3}, {%4,%5,%6,%7}, {%8,%9}, {%0,%1,%2,%3};"
        : "+f"(c[0]), "+f"(c[1]), "+f"(c[2]), "+f"(c[3])
        : "r"(a0), "r"(a1), "r"(a2), "r"(a3), "r"(b0), "r"(b1));
}
// One ldmatrix.x4: 4 m8n8(b16) tiles = 4 fragment registers.
__device__ __forceinline__ void ldsm_x4(uint32_t r[4], uint32_t addr) {
    asm volatile(
        "ldmatrix.sync.aligned.m8n8.x4.shared.b16 {%0,%1,%2,%3}, [%4];"
        : "=r"(r[0]), "=r"(r[1]), "=r"(r[2]), "=r"(r[3]) : "r"(addr));
}
__device__ __forceinline__ void cp16(uint32_t smem, const void* g) {
    asm volatile("cp.async.cg.shared.global [%0], [%1], 16;"
                 :: "r"(smem), "l"(g));
}
#define CP_COMMIT() asm volatile("cp.async.commit_group;")
#define CP_WAIT(n)  asm volatile("cp.async.wait_group %0;" :: "n"(n))

// ---------------------------------------------------------------------------
// Transpose W[h][H][D] -> g_WT[qkv][h][D][H]. grid (48, 36), 256 thr.
// ---------------------------------------------------------------------------
__global__ __launch_bounds__(256) void transpose_W(
    const float* __restrict__ Wq, const float* __restrict__ Wk,
    const float* __restrict__ Wv)
{
    const int qkv = blockIdx.y / NH_;
    const int h   = blockIdx.y % NH_;
    const float* W = (qkv == 0 ? Wq : (qkv == 1 ? Wk : Wv)) + (size_t)h * H_ * D_;
    float* WT = g_WT + (size_t)blockIdx.y * D_ * H_;

    const int kt = (blockIdx.x >> 1) * 32;   // k-tile (H dim)
    const int nt = (blockIdx.x & 1) * 32;    // n-tile (D dim)

    __shared__ float t[32][33];
    const int r  = threadIdx.x >> 3;          // 0..31
    const int c4 = (threadIdx.x & 7) * 4;     // 0,4,..28

    float4 v = *(const float4*)&W[(size_t)(kt + r) * D_ + nt + c4];
    t[r][c4 + 0] = v.x; t[r][c4 + 1] = v.y; t[r][c4 + 2] = v.z; t[r][c4 + 3] = v.w;
    __syncthreads();
    float4 o;
    o.x = t[c4 + 0][r]; o.y = t[c4 + 1][r]; o.z = t[c4 + 2][r]; o.w = t[c4 + 3][r];
    *(float4*)&WT[(size_t)(nt + r) * H_ + kt + c4] = o;
}

// ---------------------------------------------------------------------------
// Transpose g_V[bh][S][D] -> g_VT[bh][D][S]. grid (128, 48), 256 thr.
// ---------------------------------------------------------------------------
__global__ __launch_bounds__(256) void transpose_V()
{
    const int bh = blockIdx.y;
    const float* V = g_V + (size_t)bh * S_ * D_;
    float* VT = g_VT + (size_t)bh * D_ * S_;

    const int st = (blockIdx.x >> 1) * 32;   // seq tile
    const int dt = (blockIdx.x & 1) * 32;    // d tile

    __shared__ float t[32][33];
    const int r  = threadIdx.x >> 3;
    const int c4 = (threadIdx.x & 7) * 4;

    float4 v = *(const float4*)&V[(size_t)(st + r) * D_ + dt + c4];
    t[r][c4 + 0] = v.x; t[r][c4 + 1] = v.y; t[r][c4 + 2] = v.z; t[r][c4 + 3] = v.w;
    __syncthreads();
    float4 o;
    o.x = t[c4 + 0][r]; o.y = t[c4 + 1][r]; o.z = t[c4 + 2][r]; o.w = t[c4 + 3][r];
    *(float4*)&VT[(size_t)(dt + r) * S_ + st + c4] = o;
}

// ---------------------------------------------------------------------------
// QKV projection with tf32 mma + ldmatrix. grid (64, 36), 256 thr (8 warps).
// Block tile: 128 rows x 64 cols. Warp tile: 32x32 (2 m-atoms x 4 n-atoms).
// ---------------------------------------------------------------------------
#define APITCH 36   // 36 % 32 == 4; row stride 144B = 9*16B -> LDSM conflict-free
__global__ __launch_bounds__(256, 2) void qkv_proj_tc(
    const float* __restrict__ e1, const float* __restrict__ e2,
    const float* __restrict__ e3,
    const float* __restrict__ bq, const float* __restrict__ bk,
    const float* __restrict__ bv)
{
    const int h   = blockIdx.y % NH_;
    const int qkv = blockIdx.y / NH_;
    const int grp = h >> 2;

    const float* WT   = g_WT + (size_t)blockIdx.y * D_ * H_;    // [D][H]
    const float* bias = (qkv == 0 ? bq : (qkv == 1 ? bk : bv)) + (size_t)h * D_;
    float*       out  = (qkv == 0 ? g_Q : (qkv == 1 ? g_K : g_V));
    const float* x    = (grp == 0 ? e1 : (grp == 1 ? e2 : e3));

    const int m0  = blockIdx.x * 128;
    const int tid = threadIdx.x;
    const int w    = tid >> 5;
    const int lane = tid & 31;
    const int g    = lane >> 2;
    const int c    = lane & 3;
    const int m0w  = (w >> 1) * 32;   // warp row offset
    const int n0w  = (w & 1) * 32;    // warp col offset

    // ldmatrix lane->tile decomposition
    const int mrow = lane & 7;
    const int msel = lane >> 3;               // matrix index 0..3
    const int a_row = (msel & 1) * 8 + mrow;
    const int a_col = (msel >> 1) * 4;
    const int b_row = (msel >> 1) * 8 + mrow;
    const int b_col = (msel & 1) * 4;

    __shared__ float As[128 * APITCH];   // [row][k]
    __shared__ float Bs[64  * APITCH];   // [n=d][k]
    const uint32_t AsU = (uint32_t)__cvta_generic_to_shared(As);
    const uint32_t BsU = (uint32_t)__cvta_generic_to_shared(Bs);

    float Cf[2][4][4] = {};

    for (int kc = 0; kc < H_; kc += 32) {
        __syncthreads();
        // A tile 128x32 (1024 float4 -> 4/thread)
        #pragma unroll
        for (int p = 0; p < 4; p++) {
            int idx = tid + p * 256;
            int row = idx >> 3;
            int k4  = (idx & 7) * 4;
            float4 v = *(const float4*)&x[(size_t)(m0 + row) * H_ + kc + k4];
            float* d = &As[row * APITCH + k4];
            d[0] = __uint_as_float(f2tf32(v.x));
            d[1] = __uint_as_float(f2tf32(v.y));
            d[2] = __uint_as_float(f2tf32(v.z));
            d[3] = __uint_as_float(f2tf32(v.w));
        }
        // B tile 64x32 from WT (512 float4 -> 2/thread)
        #pragma unroll
        for (int p = 0; p < 2; p++) {
            int idx = tid + p * 256;
            int n   = idx >> 3;
            int k4  = (idx & 7) * 4;
            float4 v = *(const float4*)&WT[(size_t)n * H_ + kc + k4];
            float* d = &Bs[n * APITCH + k4];
            d[0] = __uint_as_float(f2tf32(v.x));
            d[1] = __uint_as_float(f2tf32(v.y));
            d[2] = __uint_as_float(f2tf32(v.z));
            d[3] = __uint_as_float(f2tf32(v.w));
        }
        __syncthreads();

        #pragma unroll
        for (int k0 = 0; k0 < 32; k0 += 8) {
            uint32_t a[2][4], b[2][4];
            #pragma unroll
            for (int ma = 0; ma < 2; ma++)
                ldsm_x4(a[ma], AsU + (uint32_t)(((m0w + ma * 16 + a_row) * APITCH
                                                 + k0 + a_col) * 4));
            #pragma unroll
            for (int p = 0; p < 2; p++)
                ldsm_x4(b[p], BsU + (uint32_t)(((n0w + p * 16 + b_row) * APITCH
                                                + k0 + b_col) * 4));
            #pragma unroll
            for (int ma = 0; ma < 2; ma++)
                #pragma unroll
                for (int na = 0; na < 4; na++)
                    mma_tf32(Cf[ma][na], a[ma][0], a[ma][1], a[ma][2], a[ma][3],
                             b[na >> 1][(na & 1) * 2], b[na >> 1][(na & 1) * 2 + 1]);
        }
    }

    const float scale = (qkv == 0) ? SCALE_ : 1.0f;
    #pragma unroll
    for (int ma = 0; ma < 2; ma++) {
        #pragma unroll
        for (int na = 0; na < 4; na++) {
            int n = n0w + na * 8 + 2 * c;
            float b0 = bias[n], b1 = bias[n + 1];
            #pragma unroll
            for (int half = 0; half < 2; half++) {
                int m = m0 + m0w + ma * 16 + g + half * 8;
                int bb = m >> 11;
                int s  = m & (S_ - 1);
                size_t base = (((size_t)bb * NH_ + h) * S_ + s) * D_ + n;
                float2 o;
                o.x = (Cf[ma][na][half * 2 + 0] + b0) * scale;
                o.y = (Cf[ma][na][half * 2 + 1] + b1) * scale;
                *(float2*)&out[base] = o;
            }
        }
    }
}

// ---------------------------------------------------------------------------
// Flash attention, tf32 mma + ldmatrix + cp.async pipelined K/V.
// grid (16, 48), 128 thr (4 warps). Warp: 32 q-rows x 64 keys.
// Single K/V buffers; K_{i+1} loads during softmax+PV_i, V_{i+1} during QK_{i+1}.
// ---------------------------------------------------------------------------
#define PITCH 68    // 68 % 32 == 4; row stride 272B = 17*16B -> LDSM conflict-free
__global__ __launch_bounds__(128) void attn_tc(float* __restrict__ out)
{
    const int bh = blockIdx.y;
    const int bb = bh / NH_;
    const int h  = bh % NH_;
    const int q0 = blockIdx.x * 128;

    extern __shared__ float sm[];
    float* Qs = sm;                  // [128][PITCH]  (q, d)
    float* Ks = Qs + 128 * PITCH;    // [64][PITCH]   (key, d)
    float* Vt = Ks + 64 * PITCH;     // [64][PITCH]   (d, key)
    float* Ps = Vt + 64 * PITCH;     // [128][PITCH]  (q, key)
    const uint32_t QsU = (uint32_t)__cvta_generic_to_shared(Qs);
    const uint32_t KsU = (uint32_t)__cvta_generic_to_shared(Ks);
    const uint32_t VtU = (uint32_t)__cvta_generic_to_shared(Vt);
    const uint32_t PsU = (uint32_t)__cvta_generic_to_shared(Ps);

    const float* Qg  = g_Q  + (size_t)bh * S_ * D_;
    const float* Kg  = g_K  + (size_t)bh * S_ * D_;
    const float* VTg = g_VT + (size_t)bh * D_ * S_;

    const int tid  = threadIdx.x;
    const int w    = tid >> 5;
    const int lane = tid & 31;
    const int g    = lane >> 2;
    const int c    = lane & 3;
    const int m0   = w * 32;

    // ldmatrix lane->tile decomposition
    const int mrow = lane & 7;
    const int msel = lane >> 3;
    const int a_row = (msel & 1) * 8 + mrow;
    const int a_col = (msel >> 1) * 4;
    const int b_row = (msel >> 1) * 8 + mrow;
    const int b_col = (msel & 1) * 4;

    const uint32_t aQ0 = QsU + (uint32_t)(((m0 + a_row) * PITCH + a_col) * 4);
    const uint32_t aQ1 = QsU + (uint32_t)(((m0 + 16 + a_row) * PITCH + a_col) * 4);
    const uint32_t aP0 = PsU + (uint32_t)(((m0 + a_row) * PITCH + a_col) * 4);
    const uint32_t aP1 = PsU + (uint32_t)(((m0 + 16 + a_row) * PITCH + a_col) * 4);

    // cp.async fill coords: 1024 16B-chunks per tile, 8 per thread
    const int f_row = tid >> 4;            // +p*8 rows
    const int f_c4  = (tid & 15) * 4;

    // -------- prologue: start K0/V0 copies, then load Q --------
    #pragma unroll
    for (int p = 0; p < 8; p++) {
        int row = f_row + p * 8;
        cp16(KsU + (uint32_t)((row * PITCH + f_c4) * 4),
             &Kg[(size_t)row * D_ + f_c4]);
        cp16(VtU + (uint32_t)((row * PITCH + f_c4) * 4),
             &VTg[(size_t)row * S_ + f_c4]);
    }
    CP_COMMIT();

    // Load Q tile 128x64 (2048 float4 -> 16/thread), tf32-rounded
    #pragma unroll
    for (int p = 0; p < 16; p++) {
        int idx = tid + p * 128;
        int row = idx >> 4;
        int c4  = (idx & 15) * 4;
        float4 v = *(const float4*)&Qg[(size_t)(q0 + row) * D_ + c4];
        float* d = &Qs[row * PITCH + c4];
        d[0] = __uint_as_float(f2tf32(v.x));
        d[1] = __uint_as_float(f2tf32(v.y));
        d[2] = __uint_as_float(f2tf32(v.z));
        d[3] = __uint_as_float(f2tf32(v.w));
    }

    float m_i[2][2], l_i[2][2];
    #pragma unroll
    for (int ma = 0; ma < 2; ma++)
        #pragma unroll
        for (int hf = 0; hf < 2; hf++) { m_i[ma][hf] = -INFINITY; l_i[ma][hf] = 0.0f; }
    float O[2][8][4] = {};

    CP_WAIT(0);
    __syncthreads();   // K0, V0, Q all visible

    for (int kt = 0; kt < S_; kt += 64) {
        const int ktn = (kt + 64 < S_) ? kt + 64 : kt;   // clamped prefetch

        // ---- S = Q K^T ----
        float Sf[2][8][4] = {};
        #pragma unroll
        for (int k0 = 0; k0 < 64; k0 += 8) {
            uint32_t a[2][4], b[4][4];
            ldsm_x4(a[0], aQ0 + (uint32_t)(k0 * 4));
            ldsm_x4(a[1], aQ1 + (uint32_t)(k0 * 4));
            #pragma unroll
            for (int p = 0; p < 4; p++)
                ldsm_x4(b[p], KsU + (uint32_t)(((p * 16 + b_row) * PITCH
                                                + k0 + b_col) * 4));
            #pragma unroll
            for (int na = 0; na < 8; na++) {
                uint32_t b0 = b[na >> 1][(na & 1) * 2];
                uint32_t b1 = b[na >> 1][(na & 1) * 2 + 1];
                #pragma unroll
                for (int ma = 0; ma < 2; ma++)
                    mma_tf32(Sf[ma][na], a[ma][0], a[ma][1], a[ma][2], a[ma][3],
                             b0, b1);
            }
        }
        __syncthreads();   // all warps done reading Ks

        // ---- prefetch K_{i+1} (overlaps softmax + PV) ----
        #pragma unroll
        for (int p = 0; p < 8; p++) {
            int row = f_row + p * 8;
            cp16(KsU + (uint32_t)((row * PITCH + f_c4) * 4),
                 &Kg[(size_t)(ktn + row) * D_ + f_c4]);
        }
        CP_COMMIT();

        // ---- online softmax ----
        #pragma unroll
        for (int ma = 0; ma < 2; ma++) {
            #pragma unroll
            for (int hf = 0; hf < 2; hf++) {
                float mx = -INFINITY;
                #pragma unroll
                for (int na = 0; na < 8; na++)
                    mx = fmaxf(mx, fmaxf(Sf[ma][na][hf * 2], Sf[ma][na][hf * 2 + 1]));
                mx = fmaxf(mx, __shfl_xor_sync(0xffffffffu, mx, 1));
                mx = fmaxf(mx, __shfl_xor_sync(0xffffffffu, mx, 2));
                float mnew  = fmaxf(m_i[ma][hf], mx);
                float alpha = __expf(m_i[ma][hf] - mnew);
                m_i[ma][hf] = mnew;
                float rs = 0.0f;
                #pragma unroll
                for (int na = 0; na < 8; na++) {
                    float p0 = __expf(Sf[ma][na][hf * 2]     - mnew);
                    float p1 = __expf(Sf[ma][na][hf * 2 + 1] - mnew);
                    Sf[ma][na][hf * 2]     = p0;
                    Sf[ma][na][hf * 2 + 1] = p1;
                    rs += p0 + p1;
                }
                rs += __shfl_xor_sync(0xffffffffu, rs, 1);
                rs += __shfl_xor_sync(0xffffffffu, rs, 2);
                l_i[ma][hf] = l_i[ma][hf] * alpha + rs;
                #pragma unroll
                for (int na = 0; na < 8; na++) {
                    O[ma][na][hf * 2]     *= alpha;
                    O[ma][na][hf * 2 + 1] *= alpha;
                }
            }
        }

        // ---- stage P (tf32-rounded) ----
        #pragma unroll
        for (int ma = 0; ma < 2; ma++) {
            int r = m0 + ma * 16 + g;
            #pragma unroll
            for (int na = 0; na < 8; na++) {
                float2 p0, p1;
                p0.x = __uint_as_float(f2tf32(Sf[ma][na][0]));
                p0.y = __uint_as_float(f2tf32(Sf[ma][na][1]));
                p1.x = __uint_as_float(f2tf32(Sf[ma][na][2]));
                p1.y = __uint_as_float(f2tf32(Sf[ma][na][3]));
                *(float2*)&Ps[r * PITCH + na * 8 + 2 * c]       = p0;
                *(float2*)&Ps[(r + 8) * PITCH + na * 8 + 2 * c] = p1;
            }
        }

        // ---- wait V_i (committed last iter / prologue), visibility barrier ----
        CP_WAIT(1);          // allow K_{i+1} group to stay pending
        __syncthreads();     // Vt visible to all warps (also orders Ps)

        // ---- O += P V ----
        #pragma unroll
        for (int k0 = 0; k0 < 64; k0 += 8) {
            uint32_t a[2][4], b[4][4];
            ldsm_x4(a[0], aP0 + (uint32_t)(k0 * 4));
            ldsm_x4(a[1], aP1 + (uint32_t)(k0 * 4));
            #pragma unroll
            for (int p = 0; p < 4; p++)
                ldsm_x4(b[p], VtU + (uint32_t)(((p * 16 + b_row) * PITCH
                                                + k0 + b_col) * 4));
            #pragma unroll
            for (int na = 0; na < 8; na++) {
                uint32_t b0 = b[na >> 1][(na & 1) * 2];
                uint32_t b1 = b[na >> 1][(na & 1) * 2 + 1];
                #pragma unroll
                for (int ma = 0; ma < 2; ma++)
                    mma_tf32(O[ma][na], a[ma][0], a[ma][1], a[ma][2], a[ma][3],
                             b0, b1);
            }
        }
        __syncthreads();   // all warps done reading Vt

        // ---- prefetch V_{i+1} (overlaps next QK + softmax) ----
        #pragma unroll
        for (int p = 0; p < 8; p++) {
            int row = f_row + p * 8;
            cp16(VtU + (uint32_t)((row * PITCH + f_c4) * 4),
                 &VTg[(size_t)row * S_ + ktn + f_c4]);
        }
        CP_COMMIT();

        // ---- wait K_{i+1}, barrier for next QK ----
        CP_WAIT(1);          // K_{i+1} done; V_{i+1} may stay pending
        __syncthreads();
    }

    // Epilogue: normalize and write out[b][s][h*64+d]
    #pragma unroll
    for (int ma = 0; ma < 2; ma++) {
        float inv0 = 1.0f / l_i[ma][0];
        float inv1 = 1.0f / l_i[ma][1];
        int r0 = q0 + m0 + ma * 16 + g;
        #pragma unroll
        for (int na = 0; na < 8; na++) {
            int d0 = na * 8 + 2 * c;
            size_t base0 = ((size_t)bb * S_ + r0) * (NH_ * D_) + h * D_ + d0;
            float2 o0; o0.x = O[ma][na][0] * inv0; o0.y = O[ma][na][1] * inv0;
            *(float2*)&out[base0] = o0;
            size_t base1 = ((size_t)bb * S_ + r0 + 8) * (NH_ * D_) + h * D_ + d0;
            float2 o1; o1.x = O[ma][na][2] * inv1; o1.y = O[ma][na][3] * inv1;
            *(float2*)&out[base1] = o1;
        }
    }
}

// ---------------------------------------------------------------------------
extern "C" void kernel_launch(void* const* d_in, const int* in_sizes, int n_in,
                              void* d_out, int out_size)
{
    const float* e1 = (const float*)d_in[0];
    const float* e2 = (const float*)d_in[1];
    const float* e3 = (const float*)d_in[2];
    const float* Wq = (const float*)d_in[3];
    const float* bq = (const float*)d_in[4];
    const float* Wk = (const float*)d_in[5];
    const float* bk = (const float*)d_in[6];
    const float* Wv = (const float*)d_in[7];
    const float* bv = (const float*)d_in[8];
    float* out = (float*)d_out;

    const int attn_smem = 384 * PITCH * sizeof(float);   // 104448 B
    static bool attr_set = false;
    if (!attr_set) {
        cudaFuncSetAttribute(attn_tc, cudaFuncAttributeMaxDynamicSharedMemorySize,
                             attn_smem);
        attr_set = true;
    }

    transpose_W<<<dim3(48, 36), 256>>>(Wq, Wk, Wv);
    qkv_proj_tc<<<dim3((B_ * S_) / 128, 36), 256>>>(e1, e2, e3, bq, bk, bv);
    transpose_V<<<dim3(128, B_ * NH_), 256>>>();
    attn_tc<<<dim3(S_ / 128, B_ * NH_), 128, attn_smem>>>(out);
}

// round 7
// speedup vs baseline: 1.4956x; 1.1162x over previous
#include <cuda_runtime.h>
#include <math.h>
#include <stdint.h>

#define B_  4
#define S_  2048
#define H_  768
#define NH_ 12
#define D_  64
#define SCALE_ 0.125f   // 1/sqrt(64)

// Scratch. Q/K layout [b][h][s][d]; VT layout [b][h][d][s]
__device__ float g_Q[(size_t)B_ * NH_ * S_ * D_];
__device__ float g_K[(size_t)B_ * NH_ * S_ * D_];
__device__ float g_VT[(size_t)B_ * NH_ * D_ * S_];
// Transposed weights [qkv][h][d][H] (tf32-rounded)
__device__ float g_WT[(size_t)3 * NH_ * D_ * H_];

// ---------------------------------------------------------------------------
__device__ __forceinline__ uint32_t f2tf32(float f) {
    uint32_t u;
    asm("cvt.rna.tf32.f32 %0, %1;" : "=r"(u) : "f"(f));
    return u;
}
__device__ __forceinline__ void mma_tf32(float c[4], uint32_t a0, uint32_t a1,
                                         uint32_t a2, uint32_t a3,
                                         uint32_t b0, uint32_t b1) {
    asm volatile(
        "mma.sync.aligned.m16n8k8.row.col.f32.tf32.tf32.f32 "
        "{%0,%1,%2,%3}, {%4,%5,%6,%7}, {%8,%9}, {%0,%1,%2,%3};"
        : "+f"(c[0]), "+f"(c[1]), "+f"(c[2]), "+f"(c[3])
        : "r"(a0), "r"(a1), "r"(a2), "r"(a3), "r"(b0), "r"(b1));
}
// One ldmatrix.x4: 4 m8n8(b16) tiles = 4 fragment registers.
__device__ __forceinline__ void ldsm_x4(uint32_t r[4], uint32_t addr) {
    asm volatile(
        "ldmatrix.sync.aligned.m8n8.x4.shared.b16 {%0,%1,%2,%3}, [%4];"
        : "=r"(r[0]), "=r"(r[1]), "=r"(r[2]), "=r"(r[3]) : "r"(addr));
}
__device__ __forceinline__ void cp16(uint32_t smem, const void* g) {
    asm volatile("cp.async.cg.shared.global [%0], [%1], 16;"
                 :: "r"(smem), "l"(g));
}
#define CP_COMMIT() asm volatile("cp.async.commit_group;")
#define CP_WAIT(n)  asm volatile("cp.async.wait_group %0;" :: "n"(n))

// ---------------------------------------------------------------------------
// Transpose W[h][H][D] -> g_WT[qkv][h][D][H], tf32-rounded. grid (48,36), 256t.
// ---------------------------------------------------------------------------
__global__ __launch_bounds__(256) void transpose_W(
    const float* __restrict__ Wq, const float* __restrict__ Wk,
    const float* __restrict__ Wv)
{
    const int qkv = blockIdx.y / NH_;
    const int h   = blockIdx.y % NH_;
    const float* W = (qkv == 0 ? Wq : (qkv == 1 ? Wk : Wv)) + (size_t)h * H_ * D_;
    float* WT = g_WT + (size_t)blockIdx.y * D_ * H_;

    const int kt = (blockIdx.x >> 1) * 32;   // k-tile (H dim)
    const int nt = (blockIdx.x & 1) * 32;    // n-tile (D dim)

    __shared__ float t[32][33];
    const int r  = threadIdx.x >> 3;          // 0..31
    const int c4 = (threadIdx.x & 7) * 4;     // 0,4,..28

    float4 v = *(const float4*)&W[(size_t)(kt + r) * D_ + nt + c4];
    t[r][c4 + 0] = v.x; t[r][c4 + 1] = v.y; t[r][c4 + 2] = v.z; t[r][c4 + 3] = v.w;
    __syncthreads();
    float4 o;
    o.x = __uint_as_float(f2tf32(t[c4 + 0][r]));
    o.y = __uint_as_float(f2tf32(t[c4 + 1][r]));
    o.z = __uint_as_float(f2tf32(t[c4 + 2][r]));
    o.w = __uint_as_float(f2tf32(t[c4 + 3][r]));
    *(float4*)&WT[(size_t)(nt + r) * H_ + kt + c4] = o;
}

// ---------------------------------------------------------------------------
// QKV projection, tf32 mma + ldmatrix + cp.async double-buffered pipeline.
// grid (64, 36), 256 thr (8 warps). Block 128x64, warp 32x32.
// V is written directly transposed into g_VT. Q/K/VT written tf32-rounded.
// ---------------------------------------------------------------------------
#define APITCH 36   // 36 % 32 == 4; row stride 144B = 9*16B -> LDSM conflict-free
#define KSTAGES (H_ / 32)   // 24
__global__ __launch_bounds__(256) void qkv_proj_tc(
    const float* __restrict__ e1, const float* __restrict__ e2,
    const float* __restrict__ e3,
    const float* __restrict__ bq, const float* __restrict__ bk,
    const float* __restrict__ bv)
{
    const int h   = blockIdx.y % NH_;
    const int qkv = blockIdx.y / NH_;
    const int grp = h >> 2;

    const float* WT   = g_WT + (size_t)blockIdx.y * D_ * H_;    // [D][H]
    const float* bias = (qkv == 0 ? bq : (qkv == 1 ? bk : bv)) + (size_t)h * D_;
    const float* x    = (grp == 0 ? e1 : (grp == 1 ? e2 : e3));

    const int m0  = blockIdx.x * 128;
    const int tid = threadIdx.x;
    const int w    = tid >> 5;
    const int lane = tid & 31;
    const int g    = lane >> 2;
    const int c    = lane & 3;
    const int m0w  = (w >> 1) * 32;   // warp row offset
    const int n0w  = (w & 1) * 32;    // warp col offset

    // ldmatrix lane->tile decomposition
    const int mrow = lane & 7;
    const int msel = lane >> 3;
    const int a_row = (msel & 1) * 8 + mrow;
    const int a_col = (msel >> 1) * 4;
    const int b_row = (msel >> 1) * 8 + mrow;
    const int b_col = (msel & 1) * 4;

    __shared__ float As[2][128 * APITCH];   // [row][k]
    __shared__ float Bs[2][64  * APITCH];   // [n=d][k]
    const uint32_t AsU[2] = { (uint32_t)__cvta_generic_to_shared(As[0]),
                              (uint32_t)__cvta_generic_to_shared(As[1]) };
    const uint32_t BsU[2] = { (uint32_t)__cvta_generic_to_shared(Bs[0]),
                              (uint32_t)__cvta_generic_to_shared(Bs[1]) };

    // cp fill coords: A = 1024 chunks (4/thr), B = 512 chunks (2/thr)
    const int fa_row = tid >> 3;          // +p*32 rows
    const int f_c4   = (tid & 7) * 4;

    // ---- prologue: stage 0 ----
    #pragma unroll
    for (int p = 0; p < 4; p++) {
        int row = fa_row + p * 32;
        cp16(AsU[0] + (uint32_t)((row * APITCH + f_c4) * 4),
             &x[(size_t)(m0 + row) * H_ + f_c4]);
    }
    #pragma unroll
    for (int p = 0; p < 2; p++) {
        int row = fa_row + p * 32;
        if (row < 64)
            cp16(BsU[0] + (uint32_t)((row * APITCH + f_c4) * 4),
                 &WT[(size_t)row * H_ + f_c4]);
    }
    CP_COMMIT();

    float Cf[2][4][4] = {};

    for (int s = 0; s < KSTAGES; s++) {
        CP_WAIT(0);
        __syncthreads();   // stage s data visible; all warps done with buf[(s+1)&1]

        // issue stage s+1 into the other buffer (overlaps compute of stage s)
        if (s + 1 < KSTAGES) {
            const int kc = (s + 1) * 32;
            const int nb = (s + 1) & 1;
            #pragma unroll
            for (int p = 0; p < 4; p++) {
                int row = fa_row + p * 32;
                cp16(AsU[nb] + (uint32_t)((row * APITCH + f_c4) * 4),
                     &x[(size_t)(m0 + row) * H_ + kc + f_c4]);
            }
            #pragma unroll
            for (int p = 0; p < 2; p++) {
                int row = fa_row + p * 32;
                if (row < 64)
                    cp16(BsU[nb] + (uint32_t)((row * APITCH + f_c4) * 4),
                         &WT[(size_t)row * H_ + kc + f_c4]);
            }
            CP_COMMIT();
        }

        const uint32_t aBase = AsU[s & 1];
        const uint32_t bBase = BsU[s & 1];
        #pragma unroll
        for (int k0 = 0; k0 < 32; k0 += 8) {
            uint32_t a[2][4], b[2][4];
            #pragma unroll
            for (int ma = 0; ma < 2; ma++)
                ldsm_x4(a[ma], aBase + (uint32_t)(((m0w + ma * 16 + a_row) * APITCH
                                                   + k0 + a_col) * 4));
            #pragma unroll
            for (int p = 0; p < 2; p++)
                ldsm_x4(b[p], bBase + (uint32_t)(((n0w + p * 16 + b_row) * APITCH
                                                  + k0 + b_col) * 4));
            #pragma unroll
            for (int ma = 0; ma < 2; ma++)
                #pragma unroll
                for (int na = 0; na < 4; na++)
                    mma_tf32(Cf[ma][na], a[ma][0], a[ma][1], a[ma][2], a[ma][3],
                             b[na >> 1][(na & 1) * 2], b[na >> 1][(na & 1) * 2 + 1]);
        }
    }

    // ---- epilogue: bias, scale, tf32-round, write ----
    if (qkv < 2) {
        float* out = (qkv == 0) ? g_Q : g_K;
        const float scale = (qkv == 0) ? SCALE_ : 1.0f;
        #pragma unroll
        for (int ma = 0; ma < 2; ma++) {
            #pragma unroll
            for (int na = 0; na < 4; na++) {
                int n = n0w + na * 8 + 2 * c;
                float b0 = bias[n], b1 = bias[n + 1];
                #pragma unroll
                for (int half = 0; half < 2; half++) {
                    int m = m0 + m0w + ma * 16 + g + half * 8;
                    int bb = m >> 11;
                    int sq = m & (S_ - 1);
                    size_t base = (((size_t)bb * NH_ + h) * S_ + sq) * D_ + n;
                    float2 o;
                    o.x = __uint_as_float(f2tf32((Cf[ma][na][half * 2 + 0] + b0) * scale));
                    o.y = __uint_as_float(f2tf32((Cf[ma][na][half * 2 + 1] + b1) * scale));
                    *(float2*)&out[base] = o;
                }
            }
        }
    } else {
        // V: write transposed into g_VT[bh][d][s]
        #pragma unroll
        for (int ma = 0; ma < 2; ma++) {
            #pragma unroll
            for (int na = 0; na < 4; na++) {
                int n = n0w + na * 8 + 2 * c;
                float b0 = bias[n], b1 = bias[n + 1];
                #pragma unroll
                for (int half = 0; half < 2; half++) {
                    int m = m0 + m0w + ma * 16 + g + half * 8;
                    int bb = m >> 11;
                    int sq = m & (S_ - 1);
                    float* VT = g_VT + ((size_t)bb * NH_ + h) * D_ * S_;
                    VT[(size_t)n * S_ + sq] =
                        __uint_as_float(f2tf32(Cf[ma][na][half * 2 + 0] + b0));
                    VT[(size_t)(n + 1) * S_ + sq] =
                        __uint_as_float(f2tf32(Cf[ma][na][half * 2 + 1] + b1));
                }
            }
        }
    }
}

// ---------------------------------------------------------------------------
// Flash attention, tf32 mma + ldmatrix + cp.async pipelined K/V. (unchanged R5)
// grid (16, 48), 128 thr (4 warps). Warp: 32 q-rows x 64 keys.
// ---------------------------------------------------------------------------
#define PITCH 68    // 68 % 32 == 4; row stride 272B = 17*16B -> LDSM conflict-free
__global__ __launch_bounds__(128) void attn_tc(float* __restrict__ out)
{
    const int bh = blockIdx.y;
    const int bb = bh / NH_;
    const int h  = bh % NH_;
    const int q0 = blockIdx.x * 128;

    extern __shared__ float sm[];
    float* Qs = sm;                  // [128][PITCH]  (q, d)
    float* Ks = Qs + 128 * PITCH;    // [64][PITCH]   (key, d)
    float* Vt = Ks + 64 * PITCH;     // [64][PITCH]   (d, key)
    float* Ps = Vt + 64 * PITCH;     // [128][PITCH]  (q, key)
    const uint32_t QsU = (uint32_t)__cvta_generic_to_shared(Qs);
    const uint32_t KsU = (uint32_t)__cvta_generic_to_shared(Ks);
    const uint32_t VtU = (uint32_t)__cvta_generic_to_shared(Vt);
    const uint32_t PsU = (uint32_t)__cvta_generic_to_shared(Ps);

    const float* Qg  = g_Q  + (size_t)bh * S_ * D_;
    const float* Kg  = g_K  + (size_t)bh * S_ * D_;
    const float* VTg = g_VT + (size_t)bh * D_ * S_;

    const int tid  = threadIdx.x;
    const int w    = tid >> 5;
    const int lane = tid & 31;
    const int g    = lane >> 2;
    const int c    = lane & 3;
    const int m0   = w * 32;

    const int mrow = lane & 7;
    const int msel = lane >> 3;
    const int a_row = (msel & 1) * 8 + mrow;
    const int a_col = (msel >> 1) * 4;
    const int b_row = (msel >> 1) * 8 + mrow;
    const int b_col = (msel & 1) * 4;

    const uint32_t aQ0 = QsU + (uint32_t)(((m0 + a_row) * PITCH + a_col) * 4);
    const uint32_t aQ1 = QsU + (uint32_t)(((m0 + 16 + a_row) * PITCH + a_col) * 4);
    const uint32_t aP0 = PsU + (uint32_t)(((m0 + a_row) * PITCH + a_col) * 4);
    const uint32_t aP1 = PsU + (uint32_t)(((m0 + 16 + a_row) * PITCH + a_col) * 4);

    const int f_row = tid >> 4;            // +p*8 rows
    const int f_c4  = (tid & 15) * 4;

    // -------- prologue: start K0/V0 copies, then load Q --------
    #pragma unroll
    for (int p = 0; p < 8; p++) {
        int row = f_row + p * 8;
        cp16(KsU + (uint32_t)((row * PITCH + f_c4) * 4),
             &Kg[(size_t)row * D_ + f_c4]);
        cp16(VtU + (uint32_t)((row * PITCH + f_c4) * 4),
             &VTg[(size_t)row * S_ + f_c4]);
    }
    CP_COMMIT();

    #pragma unroll
    for (int p = 0; p < 16; p++) {
        int idx = tid + p * 128;
        int row = idx >> 4;
        int c4  = (idx & 15) * 4;
        float4 v = *(const float4*)&Qg[(size_t)(q0 + row) * D_ + c4];
        float* d = &Qs[row * PITCH + c4];
        d[0] = __uint_as_float(f2tf32(v.x));
        d[1] = __uint_as_float(f2tf32(v.y));
        d[2] = __uint_as_float(f2tf32(v.z));
        d[3] = __uint_as_float(f2tf32(v.w));
    }

    float m_i[2][2], l_i[2][2];
    #pragma unroll
    for (int ma = 0; ma < 2; ma++)
        #pragma unroll
        for (int hf = 0; hf < 2; hf++) { m_i[ma][hf] = -INFINITY; l_i[ma][hf] = 0.0f; }
    float O[2][8][4] = {};

    CP_WAIT(0);
    __syncthreads();

    for (int kt = 0; kt < S_; kt += 64) {
        const int ktn = (kt + 64 < S_) ? kt + 64 : kt;

        // ---- S = Q K^T ----
        float Sf[2][8][4] = {};
        #pragma unroll
        for (int k0 = 0; k0 < 64; k0 += 8) {
            uint32_t a[2][4], b[4][4];
            ldsm_x4(a[0], aQ0 + (uint32_t)(k0 * 4));
            ldsm_x4(a[1], aQ1 + (uint32_t)(k0 * 4));
            #pragma unroll
            for (int p = 0; p < 4; p++)
                ldsm_x4(b[p], KsU + (uint32_t)(((p * 16 + b_row) * PITCH
                                                + k0 + b_col) * 4));
            #pragma unroll
            for (int na = 0; na < 8; na++) {
                uint32_t b0 = b[na >> 1][(na & 1) * 2];
                uint32_t b1 = b[na >> 1][(na & 1) * 2 + 1];
                #pragma unroll
                for (int ma = 0; ma < 2; ma++)
                    mma_tf32(Sf[ma][na], a[ma][0], a[ma][1], a[ma][2], a[ma][3],
                             b0, b1);
            }
        }
        __syncthreads();

        // ---- prefetch K_{i+1} ----
        #pragma unroll
        for (int p = 0; p < 8; p++) {
            int row = f_row + p * 8;
            cp16(KsU + (uint32_t)((row * PITCH + f_c4) * 4),
                 &Kg[(size_t)(ktn + row) * D_ + f_c4]);
        }
        CP_COMMIT();

        // ---- online softmax ----
        #pragma unroll
        for (int ma = 0; ma < 2; ma++) {
            #pragma unroll
            for (int hf = 0; hf < 2; hf++) {
                float mx = -INFINITY;
                #pragma unroll
                for (int na = 0; na < 8; na++)
                    mx = fmaxf(mx, fmaxf(Sf[ma][na][hf * 2], Sf[ma][na][hf * 2 + 1]));
                mx = fmaxf(mx, __shfl_xor_sync(0xffffffffu, mx, 1));
                mx = fmaxf(mx, __shfl_xor_sync(0xffffffffu, mx, 2));
                float mnew  = fmaxf(m_i[ma][hf], mx);
                float alpha = __expf(m_i[ma][hf] - mnew);
                m_i[ma][hf] = mnew;
                float rs = 0.0f;
                #pragma unroll
                for (int na = 0; na < 8; na++) {
                    float p0 = __expf(Sf[ma][na][hf * 2]     - mnew);
                    float p1 = __expf(Sf[ma][na][hf * 2 + 1] - mnew);
                    Sf[ma][na][hf * 2]     = p0;
                    Sf[ma][na][hf * 2 + 1] = p1;
                    rs += p0 + p1;
                }
                rs += __shfl_xor_sync(0xffffffffu, rs, 1);
                rs += __shfl_xor_sync(0xffffffffu, rs, 2);
                l_i[ma][hf] = l_i[ma][hf] * alpha + rs;
                #pragma unroll
                for (int na = 0; na < 8; na++) {
                    O[ma][na][hf * 2]     *= alpha;
                    O[ma][na][hf * 2 + 1] *= alpha;
                }
            }
        }

        // ---- stage P (tf32-rounded) ----
        #pragma unroll
        for (int ma = 0; ma < 2; ma++) {
            int r = m0 + ma * 16 + g;
            #pragma unroll
            for (int na = 0; na < 8; na++) {
                float2 p0, p1;
                p0.x = __uint_as_float(f2tf32(Sf[ma][na][0]));
                p0.y = __uint_as_float(f2tf32(Sf[ma][na][1]));
                p1.x = __uint_as_float(f2tf32(Sf[ma][na][2]));
                p1.y = __uint_as_float(f2tf32(Sf[ma][na][3]));
                *(float2*)&Ps[r * PITCH + na * 8 + 2 * c]       = p0;
                *(float2*)&Ps[(r + 8) * PITCH + na * 8 + 2 * c] = p1;
            }
        }

        CP_WAIT(1);
        __syncthreads();

        // ---- O += P V ----
        #pragma unroll
        for (int k0 = 0; k0 < 64; k0 += 8) {
            uint32_t a[2][4], b[4][4];
            ldsm_x4(a[0], aP0 + (uint32_t)(k0 * 4));
            ldsm_x4(a[1], aP1 + (uint32_t)(k0 * 4));
            #pragma unroll
            for (int p = 0; p < 4; p++)
                ldsm_x4(b[p], VtU + (uint32_t)(((p * 16 + b_row) * PITCH
                                                + k0 + b_col) * 4));
            #pragma unroll
            for (int na = 0; na < 8; na++) {
                uint32_t b0 = b[na >> 1][(na & 1) * 2];
                uint32_t b1 = b[na >> 1][(na & 1) * 2 + 1];
                #pragma unroll
                for (int ma = 0; ma < 2; ma++)
                    mma_tf32(O[ma][na], a[ma][0], a[ma][1], a[ma][2], a[ma][3],
                             b0, b1);
            }
        }
        __syncthreads();

        // ---- prefetch V_{i+1} ----
        #pragma unroll
        for (int p = 0; p < 8; p++) {
            int row = f_row + p * 8;
            cp16(VtU + (uint32_t)((row * PITCH + f_c4) * 4),
                 &VTg[(size_t)row * S_ + ktn + f_c4]);
        }
        CP_COMMIT();

        CP_WAIT(1);
        __syncthreads();
    }

    // Epilogue
    #pragma unroll
    for (int ma = 0; ma < 2; ma++) {
        float inv0 = 1.0f / l_i[ma][0];
        float inv1 = 1.0f / l_i[ma][1];
        int r0 = q0 + m0 + ma * 16 + g;
        #pragma unroll
        for (int na = 0; na < 8; na++) {
            int d0 = na * 8 + 2 * c;
            size_t base0 = ((size_t)bb * S_ + r0) * (NH_ * D_) + h * D_ + d0;
            float2 o0; o0.x = O[ma][na][0] * inv0; o0.y = O[ma][na][1] * inv0;
            *(float2*)&out[base0] = o0;
            size_t base1 = ((size_t)bb * S_ + r0 + 8) * (NH_ * D_) + h * D_ + d0;
            float2 o1; o1.x = O[ma][na][2] * inv1; o1.y = O[ma][na][3] * inv1;
            *(float2*)&out[base1] = o1;
        }
    }
}

// ---------------------------------------------------------------------------
extern "C" void kernel_launch(void* const* d_in, const int* in_sizes, int n_in,
                              void* d_out, int out_size)
{
    const float* e1 = (const float*)d_in[0];
    const float* e2 = (const float*)d_in[1];
    const float* e3 = (const float*)d_in[2];
    const float* Wq = (const float*)d_in[3];
    const float* bq = (const float*)d_in[4];
    const float* Wk = (const float*)d_in[5];
    const float* bk = (const float*)d_in[6];
    const float* Wv = (const float*)d_in[7];
    const float* bv = (const float*)d_in[8];
    float* out = (float*)d_out;

    const int attn_smem = 384 * PITCH * sizeof(float);   // 104448 B
    static bool attr_set = false;
    if (!attr_set) {
        cudaFuncSetAttribute(attn_tc, cudaFuncAttributeMaxDynamicSharedMemorySize,
                             attn_smem);
        attr_set = true;
    }

    transpose_W<<<dim3(48, 36), 256>>>(Wq, Wk, Wv);
    qkv_proj_tc<<<dim3((B_ * S_) / 128, 36), 256>>>(e1, e2, e3, bq, bk, bv);
    attn_tc<<<dim3(S_ / 128, B_ * NH_), 128, attn_smem>>>(out);
}